// round 12
// baseline (speedup 1.0000x reference)
#include <cuda_runtime.h>
#include <cuda_fp16.h>
#include <math.h>
#include <stdint.h>

#define HID 512
#define BSZ 64
#define TLEN 128
#define VOC 32000
#define G3H 1536
#define ENC_CTAS 128
#define DEC_CTAS 128
#define BOS 2

// scaling for fp16 split planes (powers of 2: exact)
#define SCL_MAIN 32.0f
#define SCL_RES  64.0f
#define INV_MAIN (1.0f / 1024.0f)
#define INV_RES  (1.0f / 65536.0f)

// logits tiling
#define LG_NT 256
#define LG_CTAS (VOC / LG_NT)     // 125

// decoder smem: [0,24576) Wh, [24576,49152) Wi
#define DEC_SMEM 49152

// pre-GEMM tiling (fp16 3-pass HMMA) — unchanged from R11
#define KC 32
#define PG_ROWB 80
#define PG_BROWS (2 * 128)
#define PG_AROWS (2 * 64)
#define PG_SBUF ((PG_BROWS + PG_AROWS) * PG_ROWB)  // 30720
#define PG_AOFF (PG_BROWS * PG_ROWB)               // 20480
#define PG_SMEM (2 * PG_SBUF)                      // 61440

// ---------------- scratch ----------------
__device__ float g_gi[TLEN * G3H * BSZ];
__device__ float g_hA[HID * BSZ];
__device__ float g_hB[HID * BSZ];
__device__ float g_eT[HID * BSZ];
// fragment-major W planes: uint word = {b-lo,b-hi}; uint2 per lane = {b0,b1}
// index (uint): (((n>>3)*32 + (k>>4))*32 + lane)*2 + reg
__device__ __align__(16) unsigned int g_W1f[VOC * HID / 2];
__device__ __align__(16) unsigned int g_W2f[VOC * HID / 2];
// fragment-major h planes: uint4 per lane = {a0,a1,a2,a3}
// ushort index: (((mt*32 + j)*32 + lane)*4 + reg)*2 + (k&1)
__device__ __align__(16) unsigned short g_h1f[BSZ * HID];
__device__ __align__(16) unsigned short g_h2f[BSZ * HID];
// row-major splits for the pre-GEMM path
__device__ __align__(16) unsigned short g_E1[VOC * HID];
__device__ __align__(16) unsigned short g_E2[VOC * HID];
__device__ __align__(16) unsigned short g_Wi1[G3H * HID];
__device__ __align__(16) unsigned short g_Wi2[G3H * HID];
__device__ unsigned long long g_amax2[2][BSZ];
__device__ unsigned g_bar_cnt;
__device__ unsigned g_bar_rel;
__device__ unsigned g_dcnt;
__device__ unsigned g_drel;

__device__ __forceinline__ unsigned ordered_f32(float f) {
    unsigned u = __float_as_uint(f);
    return (u & 0x80000000u) ? ~u : (u | 0x80000000u);
}
__device__ __forceinline__ unsigned short f2h(float x) {
    __half t = __float2half_rn(x);
    return *(unsigned short*)&t;
}
__device__ __forceinline__ float h2f(unsigned short u) {
    __half t = *(__half*)&u;
    return __half2float(t);
}
__device__ __forceinline__ uint32_t smem_u32(const void* p) {
    uint32_t a;
    asm("{ .reg .u64 t; cvta.to.shared.u64 t, %1; cvt.u32.u64 %0, t; }"
        : "=r"(a) : "l"(p));
    return a;
}
__device__ __forceinline__ unsigned long long pack_key(float v, int idx) {
    return ((unsigned long long)ordered_f32(v) << 32) |
           (unsigned long long)(0xFFFFFFFFu - (unsigned)idx);
}

#define MMA16816(C, A0, A1, A2, A3, B0, B1) \
    asm volatile("mma.sync.aligned.m16n8k16.row.col.f32.f16.f16.f32 " \
        "{%0,%1,%2,%3}, {%4,%5,%6,%7}, {%8,%9}, {%0,%1,%2,%3};" \
        : "+f"((C)[0]), "+f"((C)[1]), "+f"((C)[2]), "+f"((C)[3]) \
        : "r"(A0), "r"(A1), "r"(A2), "r"(A3), "r"(B0), "r"(B1))

// grid barrier for the persistent decoder (epoch-monotonic)
__device__ __forceinline__ void grid_bar(unsigned ep) {
    __threadfence();
    __syncthreads();
    if (threadIdx.x == 0) {
        unsigned v = atomicAdd(&g_dcnt, 1u);
        if (v == DEC_CTAS - 1) {
            atomicExch(&g_dcnt, 0u);
            __threadfence();
            atomicAdd(&g_drel, 1u);
        }
        while (atomicAdd(&g_drel, 0u) < ep) {}
    }
    __syncthreads();
}

// ---------------- init ----------------------------------------------------
__global__ void k_init(const float* __restrict__ emb_dec) {
    int idx = blockIdx.x * blockDim.x + threadIdx.x;
    if (idx < HID * BSZ) {
        g_hA[idx] = 0.f;
        g_eT[idx] = emb_dec[BOS * HID + (idx >> 6)];   // BOS embedding, transposed
    }
    if (idx < BSZ) { g_amax2[0][idx] = 0ull; g_amax2[1][idx] = 0ull; }
    if (idx == 0) { g_bar_cnt = 0u; g_bar_rel = 0u; g_dcnt = 0u; g_drel = 0u; }
}

// ---------------- Wout -> scaled fp16 splits in FRAGMENT-MAJOR layout ------
__global__ void k_wsplit2(const float* __restrict__ W) {
    size_t i = ((size_t)blockIdx.x * 256 + threadIdx.x) * 4;
    if (i >= (size_t)VOC * HID) return;
    const int n  = (int)(i >> 9);
    const int k0 = (int)(i & 511);          // multiple of 4
    float4 v = *(const float4*)(W + i);
    float a[4] = {v.x, v.y, v.z, v.w};
    unsigned s1[4], s2[4];
#pragma unroll
    for (int j = 0; j < 4; j++) {
        float xs = a[j] * SCL_MAIN;
        unsigned short p1 = f2h(xs);
        unsigned short p2 = f2h((xs - h2f(p1)) * SCL_RES);
        s1[j] = p1; s2[j] = p2;
    }
    const int base = ((n >> 3) * 32 + (k0 >> 4)) * 32;
    const int reg  = (k0 >> 3) & 1;
    const int l0   = ((n & 7) << 2) | ((k0 >> 1) & 3);
    const int l1   = ((n & 7) << 2) | (((k0 + 2) >> 1) & 3);
    g_W1f[(size_t)(base + l0) * 2 + reg] = s1[0] | (s1[1] << 16);
    g_W1f[(size_t)(base + l1) * 2 + reg] = s1[2] | (s1[3] << 16);
    g_W2f[(size_t)(base + l0) * 2 + reg] = s2[0] | (s2[1] << 16);
    g_W2f[(size_t)(base + l1) * 2 + reg] = s2[2] | (s2[3] << 16);
}

// ---------------- row-major splits for pre-GEMM ----------------------------
__global__ void k_esplit2(const float* __restrict__ E) {
    size_t i = ((size_t)blockIdx.x * 256 + threadIdx.x) * 4;
    if (i >= (size_t)VOC * HID) return;
    float4 v = *(const float4*)(E + i);
    float a[4] = {v.x, v.y, v.z, v.w};
#pragma unroll
    for (int j = 0; j < 4; j++) {
        float xs = a[j] * SCL_MAIN;
        unsigned short s1 = f2h(xs);
        unsigned short s2 = f2h((xs - h2f(s1)) * SCL_RES);
        g_E1[i + j] = s1; g_E2[i + j] = s2;
    }
}
__global__ void k_wisplit2(const float* __restrict__ Wi) {
    size_t i = ((size_t)blockIdx.x * 256 + threadIdx.x) * 4;
    if (i >= (size_t)G3H * HID) return;
    float4 v = *(const float4*)(Wi + i);
    float a[4] = {v.x, v.y, v.z, v.w};
#pragma unroll
    for (int j = 0; j < 4; j++) {
        float xs = a[j] * SCL_MAIN;
        unsigned short s1 = f2h(xs);
        unsigned short s2 = f2h((xs - h2f(s1)) * SCL_RES);
        g_Wi1[i + j] = s1; g_Wi2[i + j] = s2;
    }
}

// ---------------- pre-GEMM via mma.sync (unchanged from R11) ---------------
__global__ void __launch_bounds__(256, 1) pregemm_mma_k(
    const int* __restrict__ tokens, const float* __restrict__ bias)
{
    extern __shared__ __align__(128) char smem[];
    __shared__ int s_tok[64];
    const int tid = threadIdx.x, lane = tid & 31, w = tid >> 5;
    const int nblk = blockIdx.x * 128;
    const int t = blockIdx.y;
    const int g = lane >> 2, q4 = (lane & 3) * 4;

    if (tid < 64) s_tok[tid] = tokens[t * 64 + tid];
    __syncthreads();

    float cm[4][2][4], cr[4][2][4];
#pragma unroll
    for (int i = 0; i < 4; i++)
#pragma unroll
        for (int j = 0; j < 2; j++)
#pragma unroll
            for (int e = 0; e < 4; e++) { cm[i][j][e] = 0.f; cr[i][j][e] = 0.f; }

#define PG_ISSUE(kc) do {                                                      \
    char* buf = smem + (size_t)((kc) & 1) * PG_SBUF;                           \
    for (int i = tid; i < 1536; i += 256) {                                    \
        const unsigned short* src; char* dst;                                  \
        if (i < 1024) {                                                        \
            int p = i >> 9, rr = (i >> 2) & 127, q = i & 3;                    \
            const unsigned short* wp = p ? g_Wi2 : g_Wi1;                      \
            src = wp + (size_t)(nblk + rr) * HID + (kc) * KC + q * 8;          \
            dst = buf + (p * 128 + rr) * PG_ROWB + q * 16;                     \
        } else {                                                               \
            int jj = i - 1024;                                                 \
            int p = jj >> 8, rr = (jj >> 2) & 63, q = jj & 3;                  \
            const unsigned short* ep = p ? g_E2 : g_E1;                        \
            src = ep + (size_t)s_tok[rr] * HID + (kc) * KC + q * 8;            \
            dst = buf + PG_AOFF + (p * 64 + rr) * PG_ROWB + q * 16;            \
        }                                                                      \
        uint32_t d32 = smem_u32(dst);                                          \
        asm volatile("cp.async.cg.shared.global [%0], [%1], 16;"               \
                     :: "r"(d32), "l"(src));                                   \
    }                                                                          \
    asm volatile("cp.async.commit_group;");                                    \
} while (0)

    PG_ISSUE(0);

#pragma unroll 1
    for (int kc = 0; kc < 16; kc++) {
        if (kc < 15) {
            PG_ISSUE(kc + 1);
            asm volatile("cp.async.wait_group 1;");
        } else {
            asm volatile("cp.async.wait_group 0;");
        }
        __syncthreads();
        const char* buf = smem + (size_t)(kc & 1) * PG_SBUF;
#pragma unroll
        for (int k16 = 0; k16 < 2; k16++) {
            const int kb = k16 * 32 + q4;
            uint32_t w1b0[2], w1b1[2], w2b0[2], w2b1[2];
#pragma unroll
            for (int nt = 0; nt < 2; nt++) {
                const char* bp0 = buf + (size_t)(      w * 16 + nt * 8 + g) * PG_ROWB + kb;
                const char* bp1 = buf + (size_t)(128 + w * 16 + nt * 8 + g) * PG_ROWB + kb;
                w1b0[nt] = *(const uint32_t*)bp0;
                w1b1[nt] = *(const uint32_t*)(bp0 + 16);
                w2b0[nt] = *(const uint32_t*)bp1;
                w2b1[nt] = *(const uint32_t*)(bp1 + 16);
            }
#pragma unroll
            for (int mt = 0; mt < 4; mt++) {
                const char* ap1 = buf + PG_AOFF + (size_t)(     mt * 16 + g) * PG_ROWB + kb;
                const char* ap2 = buf + PG_AOFF + (size_t)(64 + mt * 16 + g) * PG_ROWB + kb;
                uint32_t e1a0 = *(const uint32_t*)ap1;
                uint32_t e1a1 = *(const uint32_t*)(ap1 + 8 * PG_ROWB);
                uint32_t e1a2 = *(const uint32_t*)(ap1 + 16);
                uint32_t e1a3 = *(const uint32_t*)(ap1 + 8 * PG_ROWB + 16);
                uint32_t e2a0 = *(const uint32_t*)ap2;
                uint32_t e2a1 = *(const uint32_t*)(ap2 + 8 * PG_ROWB);
                uint32_t e2a2 = *(const uint32_t*)(ap2 + 16);
                uint32_t e2a3 = *(const uint32_t*)(ap2 + 8 * PG_ROWB + 16);
#pragma unroll
                for (int nt = 0; nt < 2; nt++) {
                    MMA16816(cm[mt][nt], e1a0, e1a1, e1a2, e1a3, w1b0[nt], w1b1[nt]);
                    MMA16816(cr[mt][nt], e1a0, e1a1, e1a2, e1a3, w2b0[nt], w2b1[nt]);
                    MMA16816(cr[mt][nt], e2a0, e2a1, e2a2, e2a3, w1b0[nt], w1b1[nt]);
                }
            }
        }
        __syncthreads();
    }
#undef PG_ISSUE

#pragma unroll
    for (int mt = 0; mt < 4; mt++) {
        const int m0 = mt * 16 + g, m1 = m0 + 8;
#pragma unroll
        for (int nt = 0; nt < 2; nt++) {
            const int n = nblk + w * 16 + nt * 8 + (lane & 3) * 2;
            const float bb0 = bias[n], bb1 = bias[n + 1];
            float* base = g_gi + ((size_t)t * G3H + n) * 64;
            base[m0]      = cm[mt][nt][0] * INV_MAIN + cr[mt][nt][0] * INV_RES + bb0;
            base[64 + m0] = cm[mt][nt][1] * INV_MAIN + cr[mt][nt][1] * INV_RES + bb1;
            base[m1]      = cm[mt][nt][2] * INV_MAIN + cr[mt][nt][2] * INV_RES + bb0;
            base[64 + m1] = cm[mt][nt][3] * INV_MAIN + cr[mt][nt][3] * INV_RES + bb1;
        }
    }
}

// ---------------- persistent encoder recurrence (512-thr split-k) ----------
__global__ void __launch_bounds__(512, 1) enc_persist_k(
    const float* __restrict__ Whh, const float* __restrict__ bhh,
    const int* __restrict__ lengths)
{
    __shared__ float Wh[12][HID];
    __shared__ float part[3][4][64];
    const int tid = threadIdx.x;
    const int u0 = blockIdx.x * 4;

    for (int idx = tid; idx < 12 * HID; idx += 512) {
        int r = idx >> 9, k = idx & 511;
        int g = r >> 2, ui = r & 3;
        Wh[r][k] = Whh[(size_t)(g * HID + u0 + ui) * HID + k];
    }
    const int b    = tid & 63;
    const int half = (tid >> 6) & 1;
    const int ui   = tid >> 7;
    const int u    = u0 + ui;
    const int kb0  = half * 256;
    const float bR = bhh[u], bZ = bhh[HID + u], bN = bhh[2 * HID + u];
    const int len = lengths[b];
    __syncthreads();

#pragma unroll 1
    for (int t = 0; t < TLEN; t++) {
        const float* hin = (t & 1) ? g_hB : g_hA;
        float* hout      = (t & 1) ? g_hA : g_hB;
        const float* gi  = g_gi + (size_t)t * (G3H * 64);

        float hR = 0.f, hZ = 0.f, hN = 0.f;

        float hv[16];
#pragma unroll
        for (int kk = 0; kk < 16; kk++) hv[kk] = __ldcg(hin + (kb0 + kk) * 64 + b);

#pragma unroll 2
        for (int k0 = 0; k0 < 256; k0 += 16) {
            float nv[16];
            const int kn = (k0 + 16 < 256) ? (k0 + 16) : 0;
#pragma unroll
            for (int kk = 0; kk < 16; kk++)
                nv[kk] = __ldcg(hin + (kb0 + kn + kk) * 64 + b);
            const float4* wr = (const float4*)&Wh[ui][kb0 + k0];
            const float4* wz = (const float4*)&Wh[4 + ui][kb0 + k0];
            const float4* wn = (const float4*)&Wh[8 + ui][kb0 + k0];
#pragma unroll
            for (int q = 0; q < 4; q++) {
                float4 r4 = wr[q], z4 = wz[q], n4 = wn[q];
                hR = fmaf(hv[q*4+0], r4.x, hR); hR = fmaf(hv[q*4+1], r4.y, hR);
                hR = fmaf(hv[q*4+2], r4.z, hR); hR = fmaf(hv[q*4+3], r4.w, hR);
                hZ = fmaf(hv[q*4+0], z4.x, hZ); hZ = fmaf(hv[q*4+1], z4.y, hZ);
                hZ = fmaf(hv[q*4+2], z4.z, hZ); hZ = fmaf(hv[q*4+3], z4.w, hZ);
                hN = fmaf(hv[q*4+0], n4.x, hN); hN = fmaf(hv[q*4+1], n4.y, hN);
                hN = fmaf(hv[q*4+2], n4.z, hN); hN = fmaf(hv[q*4+3], n4.w, hN);
            }
#pragma unroll
            for (int kk = 0; kk < 16; kk++) hv[kk] = nv[kk];
        }

        if (half) {
            part[0][ui][b] = hR; part[1][ui][b] = hZ; part[2][ui][b] = hN;
        }
        __syncthreads();
        if (!half) {
            hR += part[0][ui][b]; hZ += part[1][ui][b]; hN += part[2][ui][b];
            float giR = gi[(size_t)u * 64 + b];
            float giZ = gi[(size_t)(HID + u) * 64 + b];
            float giN = gi[(size_t)(2 * HID + u) * 64 + b];
            float r = 1.f / (1.f + expf(-(giR + bR + hR)));
            float z = 1.f / (1.f + expf(-(giZ + bZ + hZ)));
            float n = tanhf(giN + r * (bN + hN));
            float hp = __ldcg(hin + (size_t)u * 64 + b);
            float hn = (1.f - z) * n + z * hp;
            if (t >= len) hn = hp;
            hout[(size_t)u * 64 + b] = hn;
        }

        if (t < TLEN - 1) {
            __threadfence();
            __syncthreads();
            if (tid == 0) {
                unsigned v = atomicAdd(&g_bar_cnt, 1u);
                if (v == ENC_CTAS - 1) {
                    atomicExch(&g_bar_cnt, 0u);
                    atomicAdd(&g_bar_rel, 1u);
                }
                while (atomicAdd(&g_bar_rel, 0u) < (unsigned)(t + 1)) {}
            }
            __syncthreads();
        }
    }
}

// ---------------- persistent decoder: all steps in one kernel --------------
__global__ void __launch_bounds__(256, 1) decoder_persist_k(
    const float* __restrict__ Wih, const float* __restrict__ bih,
    const float* __restrict__ Whh, const float* __restrict__ bhh,
    const float* __restrict__ emb_dec, const float* __restrict__ bias,
    float* __restrict__ out, int steps)
{
    extern __shared__ __align__(128) char smem[];
    float (*Wh)[HID] = (float(*)[HID])(smem);
    float (*Wi)[HID] = (float(*)[HID])(smem + 24576);
    __shared__ int s_tok;

    const int tid = threadIdx.x, lane = tid & 31, w = tid >> 5;
    const int cta = blockIdx.x;
    const int u0 = cta * 4;
    unsigned ep = 0;

    for (int idx = tid; idx < 12 * HID; idx += 256) {
        int r = idx >> 9, k = idx & 511;
        int g = r >> 2, ui = r & 3;
        size_t wrow = (size_t)(g * HID + u0 + ui) * HID + k;
        Wh[r][k] = Whh[wrow];
        Wi[r][k] = Wih[wrow];
    }
    const int b  = tid & 63;
    const int ui = tid >> 6;
    const int u  = u0 + ui;
    const float bhR = bhh[u], bhZ = bhh[HID + u], bhN = bhh[2 * HID + u];
    const float biR = bih[u], biZ = bih[HID + u], biN = bih[2 * HID + u];
    // A-fragment store indices for this thread's (b, u) = (m, k)
    const int fa_mt = b >> 4, fa_mq = b & 15;
    const int fa_j  = u >> 4, fa_kq = u & 15;
    const int fa_l  = ((fa_mq & 7) << 2) | ((fa_kq >> 1) & 3);
    const int fa_rg = ((fa_mq >> 3) & 1) | (((fa_kq >> 3) & 1) << 1);
    const size_t fa_idx =
        ((size_t)((fa_mt * 32 + fa_j) * 32 + fa_l) * 4 + fa_rg) * 2 + (fa_kq & 1);
    __syncthreads();

#pragma unroll 1
    for (int s = 0; s < steps; s++) {
        // ---- phase A: argmax finalize + embedding gather ----
        if (s > 0) {
            if (cta < BSZ) {
                if (tid == 0) {
                    unsigned long long key = atomicAdd(&g_amax2[s & 1][cta], 0ull);
                    s_tok = (int)(0xFFFFFFFFu - (unsigned)(key & 0xFFFFFFFFull));
                    atomicExch(&g_amax2[s & 1][cta], 0ull);
                }
                __syncthreads();
                const float* src = emb_dec + (size_t)s_tok * HID;
#pragma unroll
                for (int k = tid; k < HID; k += 256)
                    g_eT[(size_t)k * 64 + cta] = src[k];
            }
            grid_bar(++ep);
        }

        // ---- phase B: fused GRU step ----
        {
            const float* hin = (s & 1) ? g_hB : g_hA;
            float* hout      = (s & 1) ? g_hA : g_hB;
            float iR = biR, iZ = biZ, iN = biN;
            float hR = 0.f, hZ = 0.f, hN = 0.f;

            float hv[16], ev[16];
#pragma unroll
            for (int kk = 0; kk < 16; kk++) {
                hv[kk] = __ldcg(hin  + kk * 64 + b);
                ev[kk] = __ldcg(g_eT + kk * 64 + b);
            }

#pragma unroll 2
            for (int k0 = 0; k0 < HID; k0 += 16) {
                float hv2[16], ev2[16];
                const int kn = (k0 + 16 < HID) ? (k0 + 16) : 0;
#pragma unroll
                for (int kk = 0; kk < 16; kk++) {
                    hv2[kk] = __ldcg(hin  + (kn + kk) * 64 + b);
                    ev2[kk] = __ldcg(g_eT + (kn + kk) * 64 + b);
                }
                const float4* wr = (const float4*)&Wh[ui][k0];
                const float4* wz = (const float4*)&Wh[4 + ui][k0];
                const float4* wn = (const float4*)&Wh[8 + ui][k0];
                const float4* vr = (const float4*)&Wi[ui][k0];
                const float4* vz = (const float4*)&Wi[4 + ui][k0];
                const float4* vn = (const float4*)&Wi[8 + ui][k0];
#pragma unroll
                for (int q = 0; q < 4; q++) {
                    float4 r4 = wr[q], z4 = wz[q], n4 = wn[q];
                    float4 s4 = vr[q], t4 = vz[q], u4 = vn[q];
                    float hw0 = hv[q*4+0], hw1 = hv[q*4+1], hw2 = hv[q*4+2], hw3 = hv[q*4+3];
                    float ew0 = ev[q*4+0], ew1 = ev[q*4+1], ew2 = ev[q*4+2], ew3 = ev[q*4+3];
                    hR = fmaf(hw0, r4.x, hR); hR = fmaf(hw1, r4.y, hR);
                    hR = fmaf(hw2, r4.z, hR); hR = fmaf(hw3, r4.w, hR);
                    hZ = fmaf(hw0, z4.x, hZ); hZ = fmaf(hw1, z4.y, hZ);
                    hZ = fmaf(hw2, z4.z, hZ); hZ = fmaf(hw3, z4.w, hZ);
                    hN = fmaf(hw0, n4.x, hN); hN = fmaf(hw1, n4.y, hN);
                    hN = fmaf(hw2, n4.z, hN); hN = fmaf(hw3, n4.w, hN);
                    iR = fmaf(ew0, s4.x, iR); iR = fmaf(ew1, s4.y, iR);
                    iR = fmaf(ew2, s4.z, iR); iR = fmaf(ew3, s4.w, iR);
                    iZ = fmaf(ew0, t4.x, iZ); iZ = fmaf(ew1, t4.y, iZ);
                    iZ = fmaf(ew2, t4.z, iZ); iZ = fmaf(ew3, t4.w, iZ);
                    iN = fmaf(ew0, u4.x, iN); iN = fmaf(ew1, u4.y, iN);
                    iN = fmaf(ew2, u4.z, iN); iN = fmaf(ew3, u4.w, iN);
                }
#pragma unroll
                for (int kk = 0; kk < 16; kk++) { hv[kk] = hv2[kk]; ev[kk] = ev2[kk]; }
            }

            float r = 1.f / (1.f + expf(-(iR + bhR + hR)));
            float z = 1.f / (1.f + expf(-(iZ + bhZ + hZ)));
            float n = tanhf(iN + r * (bhN + hN));
            float hp = __ldcg(hin + (size_t)u * 64 + b);
            float hn = (1.f - z) * n + z * hp;
            hout[(size_t)u * 64 + b] = hn;

            // scaled fp16 split, stored in A-FRAGMENT-MAJOR layout
            float hs = hn * SCL_MAIN;
            unsigned short s1 = f2h(hs);
            unsigned short s2 = f2h((hs - h2f(s1)) * SCL_RES);
            g_h1f[fa_idx] = s1;
            g_h2f[fa_idx] = s2;
        }
        grid_bar(++ep);

        // ---- phase C: logits GEMM via direct fragment LDG ----
        if (cta < LG_CTAS) {
            const int nblk = cta * LG_NT;
            const int g = lane >> 2;
            float* ostep = out + (size_t)s * BSZ * VOC;
            const uint2* W1v = (const uint2*)g_W1f;
            const uint2* W2v = (const uint2*)g_W2f;
            const uint4* H1v = (const uint4*)g_h1f;
            const uint4* H2v = (const uint4*)g_h2f;

#pragma unroll 1
            for (int hh = 0; hh < 2; hh++) {
                const int t80 = (nblk + hh * 128 + w * 16) >> 3;
                float cm[4][2][4], cr[4][2][4];
#pragma unroll
                for (int i = 0; i < 4; i++)
#pragma unroll
                    for (int j = 0; j < 2; j++)
#pragma unroll
                        for (int e = 0; e < 4; e++) { cm[i][j][e] = 0.f; cr[i][j][e] = 0.f; }

                uint2 b1c[2], b2c[2], b1n[2], b2n[2];
                uint4 a1c[4], a2c[4], a1n[4], a2n[4];
                {
                    size_t o0 = (size_t)(t80 * 32) * 32 + lane;
                    size_t o1 = (size_t)((t80 + 1) * 32) * 32 + lane;
                    b1c[0] = __ldg(W1v + o0); b1c[1] = __ldg(W1v + o1);
                    b2c[0] = __ldg(W2v + o0); b2c[1] = __ldg(W2v + o1);
#pragma unroll
                    for (int mt = 0; mt < 4; mt++) {
                        size_t oa = (size_t)(mt * 32) * 32 + lane;
                        a1c[mt] = __ldg(H1v + oa);
                        a2c[mt] = __ldg(H2v + oa);
                    }
                }

#pragma unroll 1
                for (int j = 0; j < 32; j++) {
                    if (j < 31) {
                        size_t o0 = (size_t)(t80 * 32 + j + 1) * 32 + lane;
                        size_t o1 = (size_t)((t80 + 1) * 32 + j + 1) * 32 + lane;
                        b1n[0] = __ldg(W1v + o0); b1n[1] = __ldg(W1v + o1);
                        b2n[0] = __ldg(W2v + o0); b2n[1] = __ldg(W2v + o1);
#pragma unroll
                        for (int mt = 0; mt < 4; mt++) {
                            size_t oa = (size_t)(mt * 32 + j + 1) * 32 + lane;
                            a1n[mt] = __ldg(H1v + oa);
                            a2n[mt] = __ldg(H2v + oa);
                        }
                    }
#pragma unroll
                    for (int mt = 0; mt < 4; mt++) {
#pragma unroll
                        for (int nt = 0; nt < 2; nt++) {
                            MMA16816(cm[mt][nt], a1c[mt].x, a1c[mt].y, a1c[mt].z, a1c[mt].w,
                                     b1c[nt].x, b1c[nt].y);
                            MMA16816(cr[mt][nt], a1c[mt].x, a1c[mt].y, a1c[mt].z, a1c[mt].w,
                                     b2c[nt].x, b2c[nt].y);
                            MMA16816(cr[mt][nt], a2c[mt].x, a2c[mt].y, a2c[mt].z, a2c[mt].w,
                                     b1c[nt].x, b1c[nt].y);
                        }
                    }
                    b1c[0] = b1n[0]; b1c[1] = b1n[1];
                    b2c[0] = b2n[0]; b2c[1] = b2n[1];
#pragma unroll
                    for (int mt = 0; mt < 4; mt++) { a1c[mt] = a1n[mt]; a2c[mt] = a2n[mt]; }
                }

                // epilogue: combine planes, bias, store, per-row argmax
#pragma unroll
                for (int mt = 0; mt < 4; mt++) {
                    const int m0 = mt * 16 + g, m1 = m0 + 8;
                    unsigned long long key0 = 0ull, key1 = 0ull;
#pragma unroll
                    for (int nt = 0; nt < 2; nt++) {
                        const int col = nblk + hh * 128 + w * 16 + nt * 8 + (lane & 3) * 2;
                        const float bb0 = bias[col], bb1 = bias[col + 1];
                        float v00 = cm[mt][nt][0] * INV_MAIN + cr[mt][nt][0] * INV_RES + bb0;
                        float v01 = cm[mt][nt][1] * INV_MAIN + cr[mt][nt][1] * INV_RES + bb1;
                        float v10 = cm[mt][nt][2] * INV_MAIN + cr[mt][nt][2] * INV_RES + bb0;
                        float v11 = cm[mt][nt][3] * INV_MAIN + cr[mt][nt][3] * INV_RES + bb1;
                        *(float2*)(ostep + (size_t)m0 * VOC + col) = make_float2(v00, v01);
                        *(float2*)(ostep + (size_t)m1 * VOC + col) = make_float2(v10, v11);
                        unsigned long long k00 = pack_key(v00, col);
                        unsigned long long k01 = pack_key(v01, col + 1);
                        unsigned long long k10 = pack_key(v10, col);
                        unsigned long long k11 = pack_key(v11, col + 1);
                        if (k00 > key0) key0 = k00;
                        if (k01 > key0) key0 = k01;
                        if (k10 > key1) key1 = k10;
                        if (k11 > key1) key1 = k11;
                    }
#pragma unroll
                    for (int d = 1; d < 4; d <<= 1) {
                        unsigned long long o0 = __shfl_xor_sync(0xFFFFFFFFu, key0, d);
                        unsigned long long o1 = __shfl_xor_sync(0xFFFFFFFFu, key1, d);
                        if (o0 > key0) key0 = o0;
                        if (o1 > key1) key1 = o1;
                    }
                    if ((lane & 3) == 0) {
                        atomicMax(&g_amax2[(s + 1) & 1][m0], key0);
                        atomicMax(&g_amax2[(s + 1) & 1][m1], key1);
                    }
                }
            }
        }
        grid_bar(++ep);
    }
}

// ---------------- host orchestration --------------------------------------
extern "C" void kernel_launch(void* const* d_in, const int* in_sizes, int n_in,
                              void* d_out, int out_size) {
    const int*   batch_X = (const int*)d_in[0];
    const int*   lengths = (const int*)d_in[1];
    const float* emb_enc = (const float*)d_in[3];
    const float* Wih_e   = (const float*)d_in[4];
    const float* Whh_e   = (const float*)d_in[5];
    const float* bih_e   = (const float*)d_in[6];
    const float* bhh_e   = (const float*)d_in[7];
    const float* emb_dec = (const float*)d_in[8];
    const float* Wih_d   = (const float*)d_in[9];
    const float* Whh_d   = (const float*)d_in[10];
    const float* bih_d   = (const float*)d_in[11];
    const float* bhh_d   = (const float*)d_in[12];
    const float* Wout    = (const float*)d_in[13];
    const float* bout    = (const float*)d_in[14];
    float* out = (float*)d_out;
    const int steps = out_size / (BSZ * VOC);   // 32

    (void)in_sizes; (void)n_in;

    cudaFuncSetAttribute(decoder_persist_k,
                         cudaFuncAttributeMaxDynamicSharedMemorySize, DEC_SMEM);
    cudaFuncSetAttribute(pregemm_mma_k,
                         cudaFuncAttributeMaxDynamicSharedMemorySize, PG_SMEM);

    k_init<<<128, 256>>>(emb_dec);
    k_wsplit2<<<(VOC * HID / 4 + 255) / 256, 256>>>(Wout);
    k_esplit2<<<(VOC * HID / 4 + 255) / 256, 256>>>(emb_enc);
    k_wisplit2<<<(G3H * HID / 4 + 255) / 256, 256>>>(Wih_e);

    // encoder input pre-GEMM on tensor cores (scaled fp16 split, 3 passes)
    pregemm_mma_k<<<dim3(G3H / 128, TLEN), 256, PG_SMEM>>>(batch_X, bih_e);

    // encoder recurrence: single persistent kernel, 128 steps internally
    enc_persist_k<<<ENC_CTAS, 512>>>(Whh_e, bhh_e, lengths);
    // final hidden ends in g_hA

    // decoder: single persistent kernel, all steps internally
    decoder_persist_k<<<DEC_CTAS, 256, DEC_SMEM>>>(
        Wih_d, bih_d, Whh_d, bhh_d, emb_dec, bout, out, steps);
}

// round 13
// speedup vs baseline: 1.0382x; 1.0382x over previous
#include <cuda_runtime.h>
#include <cuda_fp16.h>
#include <math.h>
#include <stdint.h>

#define HID 512
#define BSZ 64
#define TLEN 128
#define VOC 32000
#define G3H 1536
#define ENC_CTAS 128
#define DEC_CTAS 128
#define BOS 2

// scaling for fp16 split planes (powers of 2: exact)
#define SCL_MAIN 32.0f
#define SCL_RES  64.0f
#define INV_MAIN (1.0f / 1024.0f)
#define INV_RES  (1.0f / 65536.0f)

// logits GEMM tiling (fp16 2-way split, 3 explicit passes)
#define LG_NT 256
#define LG_CTAS (VOC / LG_NT)     // 125
#define KC 32
#define ROWB 80
#define B_ROWS (2 * LG_NT)        // 512
#define A_ROWS (2 * BSZ)          // 128
#define SBUF ((B_ROWS + A_ROWS) * ROWB)   // 51200
#define A_OFF (B_ROWS * ROWB)             // 40960
#define LG_SMEM (2 * SBUF)                // 102400

// persistent decoder smem: [0,24576) Wh, [24576,49152) Wi, then logits bufs
#define DEC_WSM 49152
#define DEC_SMEM (DEC_WSM + LG_SMEM)      // 151552

// pre-GEMM tiling
#define PG_ROWB 80
#define PG_BROWS (2 * 128)
#define PG_AROWS (2 * 64)
#define PG_SBUF ((PG_BROWS + PG_AROWS) * PG_ROWB)  // 30720
#define PG_AOFF (PG_BROWS * PG_ROWB)               // 20480
#define PG_SMEM (2 * PG_SBUF)                      // 61440

// ---------------- scratch ----------------
__device__ float g_gi[TLEN * G3H * BSZ];
__device__ float g_hA[HID * BSZ];
__device__ float g_hB[HID * BSZ];
__device__ float g_eT[HID * BSZ];
__device__ __align__(16) unsigned short g_W1[VOC * HID];
__device__ __align__(16) unsigned short g_W2[VOC * HID];
__device__ __align__(16) unsigned short g_E1[VOC * HID];
__device__ __align__(16) unsigned short g_E2[VOC * HID];
__device__ __align__(16) unsigned short g_Wi1[G3H * HID];
__device__ __align__(16) unsigned short g_Wi2[G3H * HID];
__device__ __align__(16) unsigned short g_h1[BSZ * HID];
__device__ __align__(16) unsigned short g_h2[BSZ * HID];
__device__ unsigned long long g_amax2[2][BSZ];
__device__ unsigned g_bar_cnt;
__device__ unsigned g_bar_rel;
__device__ unsigned g_dcnt;
__device__ unsigned g_drel;

__device__ __forceinline__ unsigned ordered_f32(float f) {
    unsigned u = __float_as_uint(f);
    return (u & 0x80000000u) ? ~u : (u | 0x80000000u);
}
__device__ __forceinline__ unsigned short f2h(float x) {
    __half t = __float2half_rn(x);
    return *(unsigned short*)&t;
}
__device__ __forceinline__ float h2f(unsigned short u) {
    __half t = *(__half*)&u;
    return __half2float(t);
}
__device__ __forceinline__ uint32_t smem_u32(const void* p) {
    uint32_t a;
    asm("{ .reg .u64 t; cvta.to.shared.u64 t, %1; cvt.u32.u64 %0, t; }"
        : "=r"(a) : "l"(p));
    return a;
}
__device__ __forceinline__ unsigned long long pack_key(float v, int idx) {
    return ((unsigned long long)ordered_f32(v) << 32) |
           (unsigned long long)(0xFFFFFFFFu - (unsigned)idx);
}

#define MMA16816(C, A0, A1, A2, A3, B0, B1) \
    asm volatile("mma.sync.aligned.m16n8k16.row.col.f32.f16.f16.f32 " \
        "{%0,%1,%2,%3}, {%4,%5,%6,%7}, {%8,%9}, {%0,%1,%2,%3};" \
        : "+f"((C)[0]), "+f"((C)[1]), "+f"((C)[2]), "+f"((C)[3]) \
        : "r"(A0), "r"(A1), "r"(A2), "r"(A3), "r"(B0), "r"(B1))

// grid barrier for the persistent decoder (epoch-monotonic)
__device__ __forceinline__ void grid_bar(unsigned ep) {
    __threadfence();
    __syncthreads();
    if (threadIdx.x == 0) {
        unsigned v = atomicAdd(&g_dcnt, 1u);
        if (v == DEC_CTAS - 1) {
            atomicExch(&g_dcnt, 0u);
            __threadfence();
            atomicAdd(&g_drel, 1u);
        }
        while (atomicAdd(&g_drel, 0u) < ep) {}
    }
    __syncthreads();
}

// ---------------- init ----------------------------------------------------
__global__ void k_init(const float* __restrict__ emb_dec) {
    int idx = blockIdx.x * blockDim.x + threadIdx.x;
    if (idx < HID * BSZ) {
        g_hA[idx] = 0.f;
        g_eT[idx] = emb_dec[BOS * HID + (idx >> 6)];   // BOS embedding, transposed
    }
    if (idx < BSZ) { g_amax2[0][idx] = 0ull; g_amax2[1][idx] = 0ull; }
    if (idx == 0) { g_bar_cnt = 0u; g_bar_rel = 0u; g_dcnt = 0u; g_drel = 0u; }
}

// ---------------- scaled 2-way fp16 splits (row-major, device-direct) ------
__global__ void k_wsplit2(const float* __restrict__ W) {
    size_t i = ((size_t)blockIdx.x * 256 + threadIdx.x) * 4;
    if (i >= (size_t)VOC * HID) return;
    float4 v = *(const float4*)(W + i);
    float a[4] = {v.x, v.y, v.z, v.w};
#pragma unroll
    for (int j = 0; j < 4; j++) {
        float xs = a[j] * SCL_MAIN;
        unsigned short s1 = f2h(xs);
        unsigned short s2 = f2h((xs - h2f(s1)) * SCL_RES);
        g_W1[i + j] = s1; g_W2[i + j] = s2;
    }
}
__global__ void k_esplit2(const float* __restrict__ E) {
    size_t i = ((size_t)blockIdx.x * 256 + threadIdx.x) * 4;
    if (i >= (size_t)VOC * HID) return;
    float4 v = *(const float4*)(E + i);
    float a[4] = {v.x, v.y, v.z, v.w};
#pragma unroll
    for (int j = 0; j < 4; j++) {
        float xs = a[j] * SCL_MAIN;
        unsigned short s1 = f2h(xs);
        unsigned short s2 = f2h((xs - h2f(s1)) * SCL_RES);
        g_E1[i + j] = s1; g_E2[i + j] = s2;
    }
}
__global__ void k_wisplit2(const float* __restrict__ Wi) {
    size_t i = ((size_t)blockIdx.x * 256 + threadIdx.x) * 4;
    if (i >= (size_t)G3H * HID) return;
    float4 v = *(const float4*)(Wi + i);
    float a[4] = {v.x, v.y, v.z, v.w};
#pragma unroll
    for (int j = 0; j < 4; j++) {
        float xs = a[j] * SCL_MAIN;
        unsigned short s1 = f2h(xs);
        unsigned short s2 = f2h((xs - h2f(s1)) * SCL_RES);
        g_Wi1[i + j] = s1; g_Wi2[i + j] = s2;
    }
}

// ---------------- pre-GEMM via mma.sync (R11-proven) -----------------------
__global__ void __launch_bounds__(256, 1) pregemm_mma_k(
    const int* __restrict__ tokens, const float* __restrict__ bias)
{
    extern __shared__ __align__(128) char smem[];
    __shared__ int s_tok[64];
    const int tid = threadIdx.x, lane = tid & 31, w = tid >> 5;
    const int nblk = blockIdx.x * 128;
    const int t = blockIdx.y;
    const int g = lane >> 2, q4 = (lane & 3) * 4;

    if (tid < 64) s_tok[tid] = tokens[t * 64 + tid];
    __syncthreads();

    float cm[4][2][4], cr[4][2][4];
#pragma unroll
    for (int i = 0; i < 4; i++)
#pragma unroll
        for (int j = 0; j < 2; j++)
#pragma unroll
            for (int e = 0; e < 4; e++) { cm[i][j][e] = 0.f; cr[i][j][e] = 0.f; }

#define PG_ISSUE(kc) do {                                                      \
    char* buf = smem + (size_t)((kc) & 1) * PG_SBUF;                           \
    for (int i = tid; i < 1536; i += 256) {                                    \
        const unsigned short* src; char* dst;                                  \
        if (i < 1024) {                                                        \
            int p = i >> 9, rr = (i >> 2) & 127, q = i & 3;                    \
            const unsigned short* wp = p ? g_Wi2 : g_Wi1;                      \
            src = wp + (size_t)(nblk + rr) * HID + (kc) * KC + q * 8;          \
            dst = buf + (p * 128 + rr) * PG_ROWB + q * 16;                     \
        } else {                                                               \
            int jj = i - 1024;                                                 \
            int p = jj >> 8, rr = (jj >> 2) & 63, q = jj & 3;                  \
            const unsigned short* ep = p ? g_E2 : g_E1;                        \
            src = ep + (size_t)s_tok[rr] * HID + (kc) * KC + q * 8;            \
            dst = buf + PG_AOFF + (p * 64 + rr) * PG_ROWB + q * 16;            \
        }                                                                      \
        uint32_t d32 = smem_u32(dst);                                          \
        asm volatile("cp.async.cg.shared.global [%0], [%1], 16;"               \
                     :: "r"(d32), "l"(src));                                   \
    }                                                                          \
    asm volatile("cp.async.commit_group;");                                    \
} while (0)

    PG_ISSUE(0);

#pragma unroll 1
    for (int kc = 0; kc < 16; kc++) {
        if (kc < 15) {
            PG_ISSUE(kc + 1);
            asm volatile("cp.async.wait_group 1;");
        } else {
            asm volatile("cp.async.wait_group 0;");
        }
        __syncthreads();
        const char* buf = smem + (size_t)(kc & 1) * PG_SBUF;
#pragma unroll
        for (int k16 = 0; k16 < 2; k16++) {
            const int kb = k16 * 32 + q4;
            uint32_t w1b0[2], w1b1[2], w2b0[2], w2b1[2];
#pragma unroll
            for (int nt = 0; nt < 2; nt++) {
                const char* bp0 = buf + (size_t)(      w * 16 + nt * 8 + g) * PG_ROWB + kb;
                const char* bp1 = buf + (size_t)(128 + w * 16 + nt * 8 + g) * PG_ROWB + kb;
                w1b0[nt] = *(const uint32_t*)bp0;
                w1b1[nt] = *(const uint32_t*)(bp0 + 16);
                w2b0[nt] = *(const uint32_t*)bp1;
                w2b1[nt] = *(const uint32_t*)(bp1 + 16);
            }
#pragma unroll
            for (int mt = 0; mt < 4; mt++) {
                const char* ap1 = buf + PG_AOFF + (size_t)(     mt * 16 + g) * PG_ROWB + kb;
                const char* ap2 = buf + PG_AOFF + (size_t)(64 + mt * 16 + g) * PG_ROWB + kb;
                uint32_t e1a0 = *(const uint32_t*)ap1;
                uint32_t e1a1 = *(const uint32_t*)(ap1 + 8 * PG_ROWB);
                uint32_t e1a2 = *(const uint32_t*)(ap1 + 16);
                uint32_t e1a3 = *(const uint32_t*)(ap1 + 8 * PG_ROWB + 16);
                uint32_t e2a0 = *(const uint32_t*)ap2;
                uint32_t e2a1 = *(const uint32_t*)(ap2 + 8 * PG_ROWB);
                uint32_t e2a2 = *(const uint32_t*)(ap2 + 16);
                uint32_t e2a3 = *(const uint32_t*)(ap2 + 8 * PG_ROWB + 16);
#pragma unroll
                for (int nt = 0; nt < 2; nt++) {
                    MMA16816(cm[mt][nt], e1a0, e1a1, e1a2, e1a3, w1b0[nt], w1b1[nt]);
                    MMA16816(cr[mt][nt], e1a0, e1a1, e1a2, e1a3, w2b0[nt], w2b1[nt]);
                    MMA16816(cr[mt][nt], e2a0, e2a1, e2a2, e2a3, w1b0[nt], w1b1[nt]);
                }
            }
        }
        __syncthreads();
    }
#undef PG_ISSUE

#pragma unroll
    for (int mt = 0; mt < 4; mt++) {
        const int m0 = mt * 16 + g, m1 = m0 + 8;
#pragma unroll
        for (int nt = 0; nt < 2; nt++) {
            const int n = nblk + w * 16 + nt * 8 + (lane & 3) * 2;
            const float bb0 = bias[n], bb1 = bias[n + 1];
            float* base = g_gi + ((size_t)t * G3H + n) * 64;
            base[m0]      = cm[mt][nt][0] * INV_MAIN + cr[mt][nt][0] * INV_RES + bb0;
            base[64 + m0] = cm[mt][nt][1] * INV_MAIN + cr[mt][nt][1] * INV_RES + bb1;
            base[m1]      = cm[mt][nt][2] * INV_MAIN + cr[mt][nt][2] * INV_RES + bb0;
            base[64 + m1] = cm[mt][nt][3] * INV_MAIN + cr[mt][nt][3] * INV_RES + bb1;
        }
    }
}

// ---------------- persistent encoder recurrence (512-thr split-k) ----------
__global__ void __launch_bounds__(512, 1) enc_persist_k(
    const float* __restrict__ Whh, const float* __restrict__ bhh,
    const int* __restrict__ lengths)
{
    __shared__ float Wh[12][HID];
    __shared__ float part[3][4][64];
    const int tid = threadIdx.x;
    const int u0 = blockIdx.x * 4;

    for (int idx = tid; idx < 12 * HID; idx += 512) {
        int r = idx >> 9, k = idx & 511;
        int g = r >> 2, ui = r & 3;
        Wh[r][k] = Whh[(size_t)(g * HID + u0 + ui) * HID + k];
    }
    const int b    = tid & 63;
    const int half = (tid >> 6) & 1;
    const int ui   = tid >> 7;
    const int u    = u0 + ui;
    const int kb0  = half * 256;
    const float bR = bhh[u], bZ = bhh[HID + u], bN = bhh[2 * HID + u];
    const int len = lengths[b];
    __syncthreads();

#pragma unroll 1
    for (int t = 0; t < TLEN; t++) {
        const float* hin = (t & 1) ? g_hB : g_hA;
        float* hout      = (t & 1) ? g_hA : g_hB;
        const float* gi  = g_gi + (size_t)t * (G3H * 64);

        float hR = 0.f, hZ = 0.f, hN = 0.f;

        float hv[16];
#pragma unroll
        for (int kk = 0; kk < 16; kk++) hv[kk] = __ldcg(hin + (kb0 + kk) * 64 + b);

#pragma unroll 2
        for (int k0 = 0; k0 < 256; k0 += 16) {
            float nv[16];
            const int kn = (k0 + 16 < 256) ? (k0 + 16) : 0;
#pragma unroll
            for (int kk = 0; kk < 16; kk++)
                nv[kk] = __ldcg(hin + (kb0 + kn + kk) * 64 + b);
            const float4* wr = (const float4*)&Wh[ui][kb0 + k0];
            const float4* wz = (const float4*)&Wh[4 + ui][kb0 + k0];
            const float4* wn = (const float4*)&Wh[8 + ui][kb0 + k0];
#pragma unroll
            for (int q = 0; q < 4; q++) {
                float4 r4 = wr[q], z4 = wz[q], n4 = wn[q];
                hR = fmaf(hv[q*4+0], r4.x, hR); hR = fmaf(hv[q*4+1], r4.y, hR);
                hR = fmaf(hv[q*4+2], r4.z, hR); hR = fmaf(hv[q*4+3], r4.w, hR);
                hZ = fmaf(hv[q*4+0], z4.x, hZ); hZ = fmaf(hv[q*4+1], z4.y, hZ);
                hZ = fmaf(hv[q*4+2], z4.z, hZ); hZ = fmaf(hv[q*4+3], z4.w, hZ);
                hN = fmaf(hv[q*4+0], n4.x, hN); hN = fmaf(hv[q*4+1], n4.y, hN);
                hN = fmaf(hv[q*4+2], n4.z, hN); hN = fmaf(hv[q*4+3], n4.w, hN);
            }
#pragma unroll
            for (int kk = 0; kk < 16; kk++) hv[kk] = nv[kk];
        }

        if (half) {
            part[0][ui][b] = hR; part[1][ui][b] = hZ; part[2][ui][b] = hN;
        }
        __syncthreads();
        if (!half) {
            hR += part[0][ui][b]; hZ += part[1][ui][b]; hN += part[2][ui][b];
            float giR = gi[(size_t)u * 64 + b];
            float giZ = gi[(size_t)(HID + u) * 64 + b];
            float giN = gi[(size_t)(2 * HID + u) * 64 + b];
            float r = 1.f / (1.f + expf(-(giR + bR + hR)));
            float z = 1.f / (1.f + expf(-(giZ + bZ + hZ)));
            float n = tanhf(giN + r * (bN + hN));
            float hp = __ldcg(hin + (size_t)u * 64 + b);
            float hn = (1.f - z) * n + z * hp;
            if (t >= len) hn = hp;
            hout[(size_t)u * 64 + b] = hn;
        }

        if (t < TLEN - 1) {
            __threadfence();
            __syncthreads();
            if (tid == 0) {
                unsigned v = atomicAdd(&g_bar_cnt, 1u);
                if (v == ENC_CTAS - 1) {
                    atomicExch(&g_bar_cnt, 0u);
                    atomicAdd(&g_bar_rel, 1u);
                }
                while (atomicAdd(&g_bar_rel, 0u) < (unsigned)(t + 1)) {}
            }
            __syncthreads();
        }
    }
}

// ---------------- persistent decoder (512 threads, all steps) --------------
// Phase B: split-k over 2 halves (encoder pattern).
// Phase C: 16 warps, each 16 vocab cols; R11 cp.async two-stage pipeline.
__global__ void __launch_bounds__(512, 1) decoder_persist_k(
    const float* __restrict__ Wih, const float* __restrict__ bih,
    const float* __restrict__ Whh, const float* __restrict__ bhh,
    const float* __restrict__ emb_dec, const float* __restrict__ bias,
    float* __restrict__ out, int steps)
{
    extern __shared__ __align__(128) char smem[];
    float (*Wh)[HID] = (float(*)[HID])(smem);
    float (*Wi)[HID] = (float(*)[HID])(smem + 24576);
    char* lsm = smem + DEC_WSM;
    __shared__ float part[6][4][64];
    __shared__ int s_tok;

    const int tid = threadIdx.x, lane = tid & 31, w = tid >> 5;   // w 0..15
    const int cta = blockIdx.x;
    const int u0 = cta * 4;
    unsigned ep = 0;

    for (int idx = tid; idx < 12 * HID; idx += 512) {
        int r = idx >> 9, k = idx & 511;
        int g = r >> 2, ui = r & 3;
        size_t wrow = (size_t)(g * HID + u0 + ui) * HID + k;
        Wh[r][k] = Whh[wrow];
        Wi[r][k] = Wih[wrow];
    }
    const int b    = tid & 63;
    const int half = (tid >> 6) & 1;
    const int ui   = tid >> 7;           // 0..3
    const int u    = u0 + ui;
    const int kb0  = half * 256;
    const float bhR = bhh[u], bhZ = bhh[HID + u], bhN = bhh[2 * HID + u];
    const float biR = bih[u], biZ = bih[HID + u], biN = bih[2 * HID + u];
    __syncthreads();

#pragma unroll 1
    for (int s = 0; s < steps; s++) {
        // ---- phase A: argmax finalize + embedding gather ----
        if (s > 0) {
            if (cta < BSZ) {
                if (tid == 0) {
                    unsigned long long key = atomicAdd(&g_amax2[s & 1][cta], 0ull);
                    s_tok = (int)(0xFFFFFFFFu - (unsigned)(key & 0xFFFFFFFFull));
                    atomicExch(&g_amax2[s & 1][cta], 0ull);
                }
                __syncthreads();
                const float* src = emb_dec + (size_t)s_tok * HID;
#pragma unroll
                for (int k = tid; k < HID; k += 512)
                    g_eT[(size_t)k * 64 + cta] = src[k];
            }
            grid_bar(++ep);
        }

        // ---- phase B: fused GRU step, split-k over halves ----
        {
            const float* hin = (s & 1) ? g_hB : g_hA;
            float* hout      = (s & 1) ? g_hA : g_hB;
            float iR = 0.f, iZ = 0.f, iN = 0.f;
            float hR = 0.f, hZ = 0.f, hN = 0.f;

            float hv[16], ev[16];
#pragma unroll
            for (int kk = 0; kk < 16; kk++) {
                hv[kk] = __ldcg(hin  + (kb0 + kk) * 64 + b);
                ev[kk] = __ldcg(g_eT + (kb0 + kk) * 64 + b);
            }

#pragma unroll 2
            for (int k0 = 0; k0 < 256; k0 += 16) {
                float hv2[16], ev2[16];
                const int kn = (k0 + 16 < 256) ? (k0 + 16) : 0;
#pragma unroll
                for (int kk = 0; kk < 16; kk++) {
                    hv2[kk] = __ldcg(hin  + (kb0 + kn + kk) * 64 + b);
                    ev2[kk] = __ldcg(g_eT + (kb0 + kn + kk) * 64 + b);
                }
                const float4* wr = (const float4*)&Wh[ui][kb0 + k0];
                const float4* wz = (const float4*)&Wh[4 + ui][kb0 + k0];
                const float4* wn = (const float4*)&Wh[8 + ui][kb0 + k0];
                const float4* vr = (const float4*)&Wi[ui][kb0 + k0];
                const float4* vz = (const float4*)&Wi[4 + ui][kb0 + k0];
                const float4* vn = (const float4*)&Wi[8 + ui][kb0 + k0];
#pragma unroll
                for (int q = 0; q < 4; q++) {
                    float4 r4 = wr[q], z4 = wz[q], n4 = wn[q];
                    float4 s4 = vr[q], t4 = vz[q], u4 = vn[q];
                    float hw0 = hv[q*4+0], hw1 = hv[q*4+1], hw2 = hv[q*4+2], hw3 = hv[q*4+3];
                    float ew0 = ev[q*4+0], ew1 = ev[q*4+1], ew2 = ev[q*4+2], ew3 = ev[q*4+3];
                    hR = fmaf(hw0, r4.x, hR); hR = fmaf(hw1, r4.y, hR);
                    hR = fmaf(hw2, r4.z, hR); hR = fmaf(hw3, r4.w, hR);
                    hZ = fmaf(hw0, z4.x, hZ); hZ = fmaf(hw1, z4.y, hZ);
                    hZ = fmaf(hw2, z4.z, hZ); hZ = fmaf(hw3, z4.w, hZ);
                    hN = fmaf(hw0, n4.x, hN); hN = fmaf(hw1, n4.y, hN);
                    hN = fmaf(hw2, n4.z, hN); hN = fmaf(hw3, n4.w, hN);
                    iR = fmaf(ew0, s4.x, iR); iR = fmaf(ew1, s4.y, iR);
                    iR = fmaf(ew2, s4.z, iR); iR = fmaf(ew3, s4.w, iR);
                    iZ = fmaf(ew0, t4.x, iZ); iZ = fmaf(ew1, t4.y, iZ);
                    iZ = fmaf(ew2, t4.z, iZ); iZ = fmaf(ew3, t4.w, iZ);
                    iN = fmaf(ew0, u4.x, iN); iN = fmaf(ew1, u4.y, iN);
                    iN = fmaf(ew2, u4.z, iN); iN = fmaf(ew3, u4.w, iN);
                }
#pragma unroll
                for (int kk = 0; kk < 16; kk++) { hv[kk] = hv2[kk]; ev[kk] = ev2[kk]; }
            }

            if (half) {
                part[0][ui][b] = hR; part[1][ui][b] = hZ; part[2][ui][b] = hN;
                part[3][ui][b] = iR; part[4][ui][b] = iZ; part[5][ui][b] = iN;
            }
            __syncthreads();
            if (!half) {
                hR += part[0][ui][b]; hZ += part[1][ui][b]; hN += part[2][ui][b];
                iR += part[3][ui][b] + biR;
                iZ += part[4][ui][b] + biZ;
                iN += part[5][ui][b] + biN;
                float r = 1.f / (1.f + expf(-(iR + bhR + hR)));
                float z = 1.f / (1.f + expf(-(iZ + bhZ + hZ)));
                float n = tanhf(iN + r * (bhN + hN));
                float hp = __ldcg(hin + (size_t)u * 64 + b);
                float hn = (1.f - z) * n + z * hp;
                hout[(size_t)u * 64 + b] = hn;

                float hs = hn * SCL_MAIN;
                unsigned short s1 = f2h(hs);
                unsigned short s2 = f2h((hs - h2f(s1)) * SCL_RES);
                g_h1[(size_t)b * HID + u] = s1;
                g_h2[(size_t)b * HID + u] = s2;
            }
        }
        grid_bar(++ep);

        // ---- phase C: logits GEMM + bias + argmax (16 warps) ----
        if (cta < LG_CTAS) {
            const int nblk = cta * LG_NT;
            const int g = lane >> 2, q4 = (lane & 3) * 4;
            float* ostep = out + (size_t)s * BSZ * VOC;

            float cm[4][2][4], cr[4][2][4];
#pragma unroll
            for (int i = 0; i < 4; i++)
#pragma unroll
                for (int j = 0; j < 2; j++)
#pragma unroll
                    for (int e = 0; e < 4; e++) { cm[i][j][e] = 0.f; cr[i][j][e] = 0.f; }

#define LG_ISSUE(kc) do {                                                      \
    char* buf = lsm + (size_t)((kc) & 1) * SBUF;                               \
    for (int i = tid; i < 2560; i += 512) {                                    \
        const unsigned short* src; char* dst;                                  \
        if (i < 2048) {                                                        \
            int p = i >> 10, rr = (i >> 2) & 255, q = i & 3;                   \
            const unsigned short* wp = p ? g_W2 : g_W1;                        \
            src = wp + (size_t)(nblk + rr) * HID + (kc) * KC + q * 8;          \
            dst = buf + (p * 256 + rr) * ROWB + q * 16;                        \
        } else {                                                               \
            int jj = i - 2048;                                                 \
            int p = jj >> 8, rr = (jj >> 2) & 63, q = jj & 3;                  \
            const unsigned short* hp = p ? g_h2 : g_h1;                        \
            src = hp + (size_t)rr * HID + (kc) * KC + q * 8;                   \
            dst = buf + A_OFF + (p * 64 + rr) * ROWB + q * 16;                 \
        }                                                                      \
        uint32_t d32 = smem_u32(dst);                                          \
        asm volatile("cp.async.cg.shared.global [%0], [%1], 16;"               \
                     :: "r"(d32), "l"(src));                                   \
    }                                                                          \
    asm volatile("cp.async.commit_group;");                                    \
} while (0)

            LG_ISSUE(0);
#pragma unroll 1
            for (int kc = 0; kc < 16; kc++) {
                if (kc < 15) {
                    LG_ISSUE(kc + 1);
                    asm volatile("cp.async.wait_group 1;");
                } else {
                    asm volatile("cp.async.wait_group 0;");
                }
                __syncthreads();
                const char* buf = lsm + (size_t)(kc & 1) * SBUF;
#pragma unroll
                for (int k16 = 0; k16 < 2; k16++) {
                    const int kb = k16 * 32 + q4;
                    uint32_t w1b0[2], w1b1[2], w2b0[2], w2b1[2];
#pragma unroll
                    for (int nt = 0; nt < 2; nt++) {
                        const char* bp0 = buf + (size_t)(      w * 16 + nt * 8 + g) * ROWB + kb;
                        const char* bp1 = buf + (size_t)(256 + w * 16 + nt * 8 + g) * ROWB + kb;
                        w1b0[nt] = *(const uint32_t*)bp0;
                        w1b1[nt] = *(const uint32_t*)(bp0 + 16);
                        w2b0[nt] = *(const uint32_t*)bp1;
                        w2b1[nt] = *(const uint32_t*)(bp1 + 16);
                    }
#pragma unroll
                    for (int mt = 0; mt < 4; mt++) {
                        const char* ap1 = buf + A_OFF + (size_t)(     mt * 16 + g) * ROWB + kb;
                        const char* ap2 = buf + A_OFF + (size_t)(64 + mt * 16 + g) * ROWB + kb;
                        uint32_t h1a0 = *(const uint32_t*)ap1;
                        uint32_t h1a1 = *(const uint32_t*)(ap1 + 8 * ROWB);
                        uint32_t h1a2 = *(const uint32_t*)(ap1 + 16);
                        uint32_t h1a3 = *(const uint32_t*)(ap1 + 8 * ROWB + 16);
                        uint32_t h2a0 = *(const uint32_t*)ap2;
                        uint32_t h2a1 = *(const uint32_t*)(ap2 + 8 * ROWB);
                        uint32_t h2a2 = *(const uint32_t*)(ap2 + 16);
                        uint32_t h2a3 = *(const uint32_t*)(ap2 + 8 * ROWB + 16);
#pragma unroll
                        for (int nt = 0; nt < 2; nt++) {
                            MMA16816(cm[mt][nt], h1a0, h1a1, h1a2, h1a3, w1b0[nt], w1b1[nt]);
                            MMA16816(cr[mt][nt], h1a0, h1a1, h1a2, h1a3, w2b0[nt], w2b1[nt]);
                            MMA16816(cr[mt][nt], h2a0, h2a1, h2a2, h2a3, w1b0[nt], w1b1[nt]);
                        }
                    }
                }
                __syncthreads();
            }
#undef LG_ISSUE

#pragma unroll
            for (int mt = 0; mt < 4; mt++) {
                const int m0 = mt * 16 + g, m1 = m0 + 8;
                unsigned long long key0 = 0ull, key1 = 0ull;
#pragma unroll
                for (int nt = 0; nt < 2; nt++) {
                    const int col = nblk + w * 16 + nt * 8 + (lane & 3) * 2;
                    const float bb0 = bias[col], bb1 = bias[col + 1];
                    float v00 = cm[mt][nt][0] * INV_MAIN + cr[mt][nt][0] * INV_RES + bb0;
                    float v01 = cm[mt][nt][1] * INV_MAIN + cr[mt][nt][1] * INV_RES + bb1;
                    float v10 = cm[mt][nt][2] * INV_MAIN + cr[mt][nt][2] * INV_RES + bb0;
                    float v11 = cm[mt][nt][3] * INV_MAIN + cr[mt][nt][3] * INV_RES + bb1;
                    *(float2*)(ostep + (size_t)m0 * VOC + col) = make_float2(v00, v01);
                    *(float2*)(ostep + (size_t)m1 * VOC + col) = make_float2(v10, v11);
                    unsigned long long k00 = pack_key(v00, col);
                    unsigned long long k01 = pack_key(v01, col + 1);
                    unsigned long long k10 = pack_key(v10, col);
                    unsigned long long k11 = pack_key(v11, col + 1);
                    if (k00 > key0) key0 = k00;
                    if (k01 > key0) key0 = k01;
                    if (k10 > key1) key1 = k10;
                    if (k11 > key1) key1 = k11;
                }
#pragma unroll
                for (int d = 1; d < 4; d <<= 1) {
                    unsigned long long o0 = __shfl_xor_sync(0xFFFFFFFFu, key0, d);
                    unsigned long long o1 = __shfl_xor_sync(0xFFFFFFFFu, key1, d);
                    if (o0 > key0) key0 = o0;
                    if (o1 > key1) key1 = o1;
                }
                if ((lane & 3) == 0) {
                    atomicMax(&g_amax2[(s + 1) & 1][m0], key0);
                    atomicMax(&g_amax2[(s + 1) & 1][m1], key1);
                }
            }
        }
        grid_bar(++ep);
    }
}

// ---------------- host orchestration --------------------------------------
extern "C" void kernel_launch(void* const* d_in, const int* in_sizes, int n_in,
                              void* d_out, int out_size) {
    const int*   batch_X = (const int*)d_in[0];
    const int*   lengths = (const int*)d_in[1];
    const float* emb_enc = (const float*)d_in[3];
    const float* Wih_e   = (const float*)d_in[4];
    const float* Whh_e   = (const float*)d_in[5];
    const float* bih_e   = (const float*)d_in[6];
    const float* bhh_e   = (const float*)d_in[7];
    const float* emb_dec = (const float*)d_in[8];
    const float* Wih_d   = (const float*)d_in[9];
    const float* Whh_d   = (const float*)d_in[10];
    const float* bih_d   = (const float*)d_in[11];
    const float* bhh_d   = (const float*)d_in[12];
    const float* Wout    = (const float*)d_in[13];
    const float* bout    = (const float*)d_in[14];
    float* out = (float*)d_out;
    const int steps = out_size / (BSZ * VOC);   // 32

    (void)in_sizes; (void)n_in;

    cudaFuncSetAttribute(decoder_persist_k,
                         cudaFuncAttributeMaxDynamicSharedMemorySize, DEC_SMEM);
    cudaFuncSetAttribute(pregemm_mma_k,
                         cudaFuncAttributeMaxDynamicSharedMemorySize, PG_SMEM);

    k_init<<<128, 256>>>(emb_dec);
    k_wsplit2<<<(VOC * HID / 4 + 255) / 256, 256>>>(Wout);
    k_esplit2<<<(VOC * HID / 4 + 255) / 256, 256>>>(emb_enc);
    k_wisplit2<<<(G3H * HID / 4 + 255) / 256, 256>>>(Wih_e);

    // encoder input pre-GEMM on tensor cores (scaled fp16 split, 3 passes)
    pregemm_mma_k<<<dim3(G3H / 128, TLEN), 256, PG_SMEM>>>(batch_X, bih_e);

    // encoder recurrence: single persistent kernel, 128 steps internally
    enc_persist_k<<<ENC_CTAS, 512>>>(Whh_e, bhh_e, lengths);
    // final hidden ends in g_hA

    // decoder: single persistent kernel, all steps internally
    decoder_persist_k<<<DEC_CTAS, 512, DEC_SMEM>>>(
        Wih_d, bih_d, Whh_d, bhh_d, emb_dec, bout, out, steps);
}

// round 14
// speedup vs baseline: 1.1042x; 1.0636x over previous
#include <cuda_runtime.h>
#include <cuda_fp16.h>
#include <math.h>
#include <stdint.h>

#define HID 512
#define BSZ 64
#define TLEN 128
#define VOC 32000
#define G3H 1536
#define ENC_CTAS 128
#define DEC_CTAS 128
#define BOS 2

// scaling for fp16 split planes (powers of 2: exact)
#define SCL_MAIN 32.0f
#define SCL_RES  64.0f
#define INV_MAIN (1.0f / 1024.0f)
#define INV_RES  (1.0f / 65536.0f)

// logits GEMM tiling (fp16 2-way split, 3 explicit passes)
#define LG_NT 256
#define LG_CTAS (VOC / LG_NT)     // 125
#define KC 32
#define ROWB 80
#define B_ROWS (2 * LG_NT)        // 512
#define A_ROWS (2 * BSZ)          // 128
#define SBUF ((B_ROWS + A_ROWS) * ROWB)   // 51200
#define A_OFF (B_ROWS * ROWB)             // 40960

// persistent decoder smem: [0,24576) Wh, [24576,49152) Wi, then 3 logits bufs
#define DEC_WSM 49152
#define DEC_SMEM (DEC_WSM + 3 * SBUF)     // 202752

// pre-GEMM tiling
#define PG_ROWB 80
#define PG_BROWS (2 * 128)
#define PG_AROWS (2 * 64)
#define PG_SBUF ((PG_BROWS + PG_AROWS) * PG_ROWB)  // 30720
#define PG_AOFF (PG_BROWS * PG_ROWB)               // 20480
#define PG_SMEM (2 * PG_SBUF)                      // 61440

// ---------------- scratch ----------------
__device__ float g_gi[TLEN * G3H * BSZ];
__device__ float g_hA[HID * BSZ];
__device__ float g_hB[HID * BSZ];
__device__ float g_eT[HID * BSZ];
__device__ __align__(16) unsigned short g_W1[VOC * HID];
__device__ __align__(16) unsigned short g_W2[VOC * HID];
__device__ __align__(16) unsigned short g_E1[VOC * HID];
__device__ __align__(16) unsigned short g_E2[VOC * HID];
__device__ __align__(16) unsigned short g_Wi1[G3H * HID];
__device__ __align__(16) unsigned short g_Wi2[G3H * HID];
__device__ __align__(16) unsigned short g_h1[BSZ * HID];
__device__ __align__(16) unsigned short g_h2[BSZ * HID];
__device__ unsigned long long g_amax2[2][BSZ];
__device__ unsigned g_bar_cnt;
__device__ unsigned g_bar_rel;
__device__ unsigned g_dcnt;
__device__ unsigned g_drel;

__device__ __forceinline__ unsigned ordered_f32(float f) {
    unsigned u = __float_as_uint(f);
    return (u & 0x80000000u) ? ~u : (u | 0x80000000u);
}
__device__ __forceinline__ unsigned short f2h(float x) {
    __half t = __float2half_rn(x);
    return *(unsigned short*)&t;
}
__device__ __forceinline__ float h2f(unsigned short u) {
    __half t = *(__half*)&u;
    return __half2float(t);
}
__device__ __forceinline__ uint32_t smem_u32(const void* p) {
    uint32_t a;
    asm("{ .reg .u64 t; cvta.to.shared.u64 t, %1; cvt.u32.u64 %0, t; }"
        : "=r"(a) : "l"(p));
    return a;
}
__device__ __forceinline__ unsigned long long pack_key(float v, int idx) {
    return ((unsigned long long)ordered_f32(v) << 32) |
           (unsigned long long)(0xFFFFFFFFu - (unsigned)idx);
}

#define MMA16816(C, A0, A1, A2, A3, B0, B1) \
    asm volatile("mma.sync.aligned.m16n8k16.row.col.f32.f16.f16.f32 " \
        "{%0,%1,%2,%3}, {%4,%5,%6,%7}, {%8,%9}, {%0,%1,%2,%3};" \
        : "+f"((C)[0]), "+f"((C)[1]), "+f"((C)[2]), "+f"((C)[3]) \
        : "r"(A0), "r"(A1), "r"(A2), "r"(A3), "r"(B0), "r"(B1))

// grid barrier for the persistent decoder (epoch-monotonic)
__device__ __forceinline__ void grid_bar(unsigned ep) {
    __threadfence();
    __syncthreads();
    if (threadIdx.x == 0) {
        unsigned v = atomicAdd(&g_dcnt, 1u);
        if (v == DEC_CTAS - 1) {
            atomicExch(&g_dcnt, 0u);
            __threadfence();
            atomicAdd(&g_drel, 1u);
        }
        while (atomicAdd(&g_drel, 0u) < ep) {}
    }
    __syncthreads();
}

// ---------------- init ----------------------------------------------------
__global__ void k_init(const float* __restrict__ emb_dec) {
    int idx = blockIdx.x * blockDim.x + threadIdx.x;
    if (idx < HID * BSZ) {
        g_hA[idx] = 0.f;
        g_eT[idx] = emb_dec[BOS * HID + (idx >> 6)];   // BOS embedding, transposed
    }
    if (idx < BSZ) { g_amax2[0][idx] = 0ull; g_amax2[1][idx] = 0ull; }
    if (idx == 0) { g_bar_cnt = 0u; g_bar_rel = 0u; g_dcnt = 0u; g_drel = 0u; }
}

// ---------------- scaled 2-way fp16 splits (row-major, device-direct) ------
__global__ void k_wsplit2(const float* __restrict__ W) {
    size_t i = ((size_t)blockIdx.x * 256 + threadIdx.x) * 4;
    if (i >= (size_t)VOC * HID) return;
    float4 v = *(const float4*)(W + i);
    float a[4] = {v.x, v.y, v.z, v.w};
#pragma unroll
    for (int j = 0; j < 4; j++) {
        float xs = a[j] * SCL_MAIN;
        unsigned short s1 = f2h(xs);
        unsigned short s2 = f2h((xs - h2f(s1)) * SCL_RES);
        g_W1[i + j] = s1; g_W2[i + j] = s2;
    }
}
__global__ void k_esplit2(const float* __restrict__ E) {
    size_t i = ((size_t)blockIdx.x * 256 + threadIdx.x) * 4;
    if (i >= (size_t)VOC * HID) return;
    float4 v = *(const float4*)(E + i);
    float a[4] = {v.x, v.y, v.z, v.w};
#pragma unroll
    for (int j = 0; j < 4; j++) {
        float xs = a[j] * SCL_MAIN;
        unsigned short s1 = f2h(xs);
        unsigned short s2 = f2h((xs - h2f(s1)) * SCL_RES);
        g_E1[i + j] = s1; g_E2[i + j] = s2;
    }
}
__global__ void k_wisplit2(const float* __restrict__ Wi) {
    size_t i = ((size_t)blockIdx.x * 256 + threadIdx.x) * 4;
    if (i >= (size_t)G3H * HID) return;
    float4 v = *(const float4*)(Wi + i);
    float a[4] = {v.x, v.y, v.z, v.w};
#pragma unroll
    for (int j = 0; j < 4; j++) {
        float xs = a[j] * SCL_MAIN;
        unsigned short s1 = f2h(xs);
        unsigned short s2 = f2h((xs - h2f(s1)) * SCL_RES);
        g_Wi1[i + j] = s1; g_Wi2[i + j] = s2;
    }
}

// ---------------- pre-GEMM via mma.sync (R11-proven) -----------------------
__global__ void __launch_bounds__(256, 1) pregemm_mma_k(
    const int* __restrict__ tokens, const float* __restrict__ bias)
{
    extern __shared__ __align__(128) char smem[];
    __shared__ int s_tok[64];
    const int tid = threadIdx.x, lane = tid & 31, w = tid >> 5;
    const int nblk = blockIdx.x * 128;
    const int t = blockIdx.y;
    const int g = lane >> 2, q4 = (lane & 3) * 4;

    if (tid < 64) s_tok[tid] = tokens[t * 64 + tid];
    __syncthreads();

    float cm[4][2][4], cr[4][2][4];
#pragma unroll
    for (int i = 0; i < 4; i++)
#pragma unroll
        for (int j = 0; j < 2; j++)
#pragma unroll
            for (int e = 0; e < 4; e++) { cm[i][j][e] = 0.f; cr[i][j][e] = 0.f; }

#define PG_ISSUE(kc) do {                                                      \
    char* buf = smem + (size_t)((kc) & 1) * PG_SBUF;                           \
    for (int i = tid; i < 1536; i += 256) {                                    \
        const unsigned short* src; char* dst;                                  \
        if (i < 1024) {                                                        \
            int p = i >> 9, rr = (i >> 2) & 127, q = i & 3;                    \
            const unsigned short* wp = p ? g_Wi2 : g_Wi1;                      \
            src = wp + (size_t)(nblk + rr) * HID + (kc) * KC + q * 8;          \
            dst = buf + (p * 128 + rr) * PG_ROWB + q * 16;                     \
        } else {                                                               \
            int jj = i - 1024;                                                 \
            int p = jj >> 8, rr = (jj >> 2) & 63, q = jj & 3;                  \
            const unsigned short* ep = p ? g_E2 : g_E1;                        \
            src = ep + (size_t)s_tok[rr] * HID + (kc) * KC + q * 8;            \
            dst = buf + PG_AOFF + (p * 64 + rr) * PG_ROWB + q * 16;            \
        }                                                                      \
        uint32_t d32 = smem_u32(dst);                                          \
        asm volatile("cp.async.cg.shared.global [%0], [%1], 16;"               \
                     :: "r"(d32), "l"(src));                                   \
    }                                                                          \
    asm volatile("cp.async.commit_group;");                                    \
} while (0)

    PG_ISSUE(0);

#pragma unroll 1
    for (int kc = 0; kc < 16; kc++) {
        if (kc < 15) {
            PG_ISSUE(kc + 1);
            asm volatile("cp.async.wait_group 1;");
        } else {
            asm volatile("cp.async.wait_group 0;");
        }
        __syncthreads();
        const char* buf = smem + (size_t)(kc & 1) * PG_SBUF;
#pragma unroll
        for (int k16 = 0; k16 < 2; k16++) {
            const int kb = k16 * 32 + q4;
            uint32_t w1b0[2], w1b1[2], w2b0[2], w2b1[2];
#pragma unroll
            for (int nt = 0; nt < 2; nt++) {
                const char* bp0 = buf + (size_t)(      w * 16 + nt * 8 + g) * PG_ROWB + kb;
                const char* bp1 = buf + (size_t)(128 + w * 16 + nt * 8 + g) * PG_ROWB + kb;
                w1b0[nt] = *(const uint32_t*)bp0;
                w1b1[nt] = *(const uint32_t*)(bp0 + 16);
                w2b0[nt] = *(const uint32_t*)bp1;
                w2b1[nt] = *(const uint32_t*)(bp1 + 16);
            }
#pragma unroll
            for (int mt = 0; mt < 4; mt++) {
                const char* ap1 = buf + PG_AOFF + (size_t)(     mt * 16 + g) * PG_ROWB + kb;
                const char* ap2 = buf + PG_AOFF + (size_t)(64 + mt * 16 + g) * PG_ROWB + kb;
                uint32_t e1a0 = *(const uint32_t*)ap1;
                uint32_t e1a1 = *(const uint32_t*)(ap1 + 8 * PG_ROWB);
                uint32_t e1a2 = *(const uint32_t*)(ap1 + 16);
                uint32_t e1a3 = *(const uint32_t*)(ap1 + 8 * PG_ROWB + 16);
                uint32_t e2a0 = *(const uint32_t*)ap2;
                uint32_t e2a1 = *(const uint32_t*)(ap2 + 8 * PG_ROWB);
                uint32_t e2a2 = *(const uint32_t*)(ap2 + 16);
                uint32_t e2a3 = *(const uint32_t*)(ap2 + 8 * PG_ROWB + 16);
#pragma unroll
                for (int nt = 0; nt < 2; nt++) {
                    MMA16816(cm[mt][nt], e1a0, e1a1, e1a2, e1a3, w1b0[nt], w1b1[nt]);
                    MMA16816(cr[mt][nt], e1a0, e1a1, e1a2, e1a3, w2b0[nt], w2b1[nt]);
                    MMA16816(cr[mt][nt], e2a0, e2a1, e2a2, e2a3, w1b0[nt], w1b1[nt]);
                }
            }
        }
        __syncthreads();
    }
#undef PG_ISSUE

#pragma unroll
    for (int mt = 0; mt < 4; mt++) {
        const int m0 = mt * 16 + g, m1 = m0 + 8;
#pragma unroll
        for (int nt = 0; nt < 2; nt++) {
            const int n = nblk + w * 16 + nt * 8 + (lane & 3) * 2;
            const float bb0 = bias[n], bb1 = bias[n + 1];
            float* base = g_gi + ((size_t)t * G3H + n) * 64;
            base[m0]      = cm[mt][nt][0] * INV_MAIN + cr[mt][nt][0] * INV_RES + bb0;
            base[64 + m0] = cm[mt][nt][1] * INV_MAIN + cr[mt][nt][1] * INV_RES + bb1;
            base[m1]      = cm[mt][nt][2] * INV_MAIN + cr[mt][nt][2] * INV_RES + bb0;
            base[64 + m1] = cm[mt][nt][3] * INV_MAIN + cr[mt][nt][3] * INV_RES + bb1;
        }
    }
}

// ---------------- persistent encoder recurrence (512-thr split-k) ----------
__global__ void __launch_bounds__(512, 1) enc_persist_k(
    const float* __restrict__ Whh, const float* __restrict__ bhh,
    const int* __restrict__ lengths)
{
    __shared__ float Wh[12][HID];
    __shared__ float part[3][4][64];
    const int tid = threadIdx.x;
    const int u0 = blockIdx.x * 4;

    for (int idx = tid; idx < 12 * HID; idx += 512) {
        int r = idx >> 9, k = idx & 511;
        int g = r >> 2, ui = r & 3;
        Wh[r][k] = Whh[(size_t)(g * HID + u0 + ui) * HID + k];
    }
    const int b    = tid & 63;
    const int half = (tid >> 6) & 1;
    const int ui   = tid >> 7;
    const int u    = u0 + ui;
    const int kb0  = half * 256;
    const float bR = bhh[u], bZ = bhh[HID + u], bN = bhh[2 * HID + u];
    const int len = lengths[b];
    __syncthreads();

#pragma unroll 1
    for (int t = 0; t < TLEN; t++) {
        const float* hin = (t & 1) ? g_hB : g_hA;
        float* hout      = (t & 1) ? g_hA : g_hB;
        const float* gi  = g_gi + (size_t)t * (G3H * 64);

        float hR = 0.f, hZ = 0.f, hN = 0.f;

        float hv[16];
#pragma unroll
        for (int kk = 0; kk < 16; kk++) hv[kk] = __ldcg(hin + (kb0 + kk) * 64 + b);

#pragma unroll 2
        for (int k0 = 0; k0 < 256; k0 += 16) {
            float nv[16];
            const int kn = (k0 + 16 < 256) ? (k0 + 16) : 0;
#pragma unroll
            for (int kk = 0; kk < 16; kk++)
                nv[kk] = __ldcg(hin + (kb0 + kn + kk) * 64 + b);
            const float4* wr = (const float4*)&Wh[ui][kb0 + k0];
            const float4* wz = (const float4*)&Wh[4 + ui][kb0 + k0];
            const float4* wn = (const float4*)&Wh[8 + ui][kb0 + k0];
#pragma unroll
            for (int q = 0; q < 4; q++) {
                float4 r4 = wr[q], z4 = wz[q], n4 = wn[q];
                hR = fmaf(hv[q*4+0], r4.x, hR); hR = fmaf(hv[q*4+1], r4.y, hR);
                hR = fmaf(hv[q*4+2], r4.z, hR); hR = fmaf(hv[q*4+3], r4.w, hR);
                hZ = fmaf(hv[q*4+0], z4.x, hZ); hZ = fmaf(hv[q*4+1], z4.y, hZ);
                hZ = fmaf(hv[q*4+2], z4.z, hZ); hZ = fmaf(hv[q*4+3], z4.w, hZ);
                hN = fmaf(hv[q*4+0], n4.x, hN); hN = fmaf(hv[q*4+1], n4.y, hN);
                hN = fmaf(hv[q*4+2], n4.z, hN); hN = fmaf(hv[q*4+3], n4.w, hN);
            }
#pragma unroll
            for (int kk = 0; kk < 16; kk++) hv[kk] = nv[kk];
        }

        if (half) {
            part[0][ui][b] = hR; part[1][ui][b] = hZ; part[2][ui][b] = hN;
        }
        __syncthreads();
        if (!half) {
            hR += part[0][ui][b]; hZ += part[1][ui][b]; hN += part[2][ui][b];
            float giR = gi[(size_t)u * 64 + b];
            float giZ = gi[(size_t)(HID + u) * 64 + b];
            float giN = gi[(size_t)(2 * HID + u) * 64 + b];
            float r = 1.f / (1.f + expf(-(giR + bR + hR)));
            float z = 1.f / (1.f + expf(-(giZ + bZ + hZ)));
            float n = tanhf(giN + r * (bN + hN));
            float hp = __ldcg(hin + (size_t)u * 64 + b);
            float hn = (1.f - z) * n + z * hp;
            if (t >= len) hn = hp;
            hout[(size_t)u * 64 + b] = hn;
        }

        if (t < TLEN - 1) {
            __threadfence();
            __syncthreads();
            if (tid == 0) {
                unsigned v = atomicAdd(&g_bar_cnt, 1u);
                if (v == ENC_CTAS - 1) {
                    atomicExch(&g_bar_cnt, 0u);
                    atomicAdd(&g_bar_rel, 1u);
                }
                while (atomicAdd(&g_bar_rel, 0u) < (unsigned)(t + 1)) {}
            }
            __syncthreads();
        }
    }
}

// ---------------- persistent decoder (R11 structure; 3-stage phase C) ------
__global__ void __launch_bounds__(256, 1) decoder_persist_k(
    const float* __restrict__ Wih, const float* __restrict__ bih,
    const float* __restrict__ Whh, const float* __restrict__ bhh,
    const float* __restrict__ emb_dec, const float* __restrict__ bias,
    float* __restrict__ out, int steps)
{
    extern __shared__ __align__(128) char smem[];
    float (*Wh)[HID] = (float(*)[HID])(smem);
    float (*Wi)[HID] = (float(*)[HID])(smem + 24576);
    char* lsm = smem + DEC_WSM;
    __shared__ int s_tok;

    const int tid = threadIdx.x, lane = tid & 31, w = tid >> 5;
    const int cta = blockIdx.x;
    const int u0 = cta * 4;
    unsigned ep = 0;

    for (int idx = tid; idx < 12 * HID; idx += 256) {
        int r = idx >> 9, k = idx & 511;
        int g = r >> 2, ui = r & 3;
        size_t wrow = (size_t)(g * HID + u0 + ui) * HID + k;
        Wh[r][k] = Whh[wrow];
        Wi[r][k] = Wih[wrow];
    }
    const int b  = tid & 63;
    const int ui = tid >> 6;
    const int u  = u0 + ui;
    const float bhR = bhh[u], bhZ = bhh[HID + u], bhN = bhh[2 * HID + u];
    const float biR = bih[u], biZ = bih[HID + u], biN = bih[2 * HID + u];
    __syncthreads();

#pragma unroll 1
    for (int s = 0; s < steps; s++) {
        // ---- phase A: argmax finalize + embedding gather ----
        if (s > 0) {
            if (cta < BSZ) {
                if (tid == 0) {
                    unsigned long long key = atomicAdd(&g_amax2[s & 1][cta], 0ull);
                    s_tok = (int)(0xFFFFFFFFu - (unsigned)(key & 0xFFFFFFFFull));
                    atomicExch(&g_amax2[s & 1][cta], 0ull);
                }
                __syncthreads();
                const float* src = emb_dec + (size_t)s_tok * HID;
#pragma unroll
                for (int k = tid; k < HID; k += 256)
                    g_eT[(size_t)k * 64 + cta] = src[k];
            }
            grid_bar(++ep);
        }

        // ---- phase B: fused GRU step (R11) ----
        {
            const float* hin = (s & 1) ? g_hB : g_hA;
            float* hout      = (s & 1) ? g_hA : g_hB;
            float iR = biR, iZ = biZ, iN = biN;
            float hR = 0.f, hZ = 0.f, hN = 0.f;

            float hv[16], ev[16];
#pragma unroll
            for (int kk = 0; kk < 16; kk++) {
                hv[kk] = __ldcg(hin  + kk * 64 + b);
                ev[kk] = __ldcg(g_eT + kk * 64 + b);
            }

#pragma unroll 2
            for (int k0 = 0; k0 < HID; k0 += 16) {
                float hv2[16], ev2[16];
                const int kn = (k0 + 16 < HID) ? (k0 + 16) : 0;
#pragma unroll
                for (int kk = 0; kk < 16; kk++) {
                    hv2[kk] = __ldcg(hin  + (kn + kk) * 64 + b);
                    ev2[kk] = __ldcg(g_eT + (kn + kk) * 64 + b);
                }
                const float4* wr = (const float4*)&Wh[ui][k0];
                const float4* wz = (const float4*)&Wh[4 + ui][k0];
                const float4* wn = (const float4*)&Wh[8 + ui][k0];
                const float4* vr = (const float4*)&Wi[ui][k0];
                const float4* vz = (const float4*)&Wi[4 + ui][k0];
                const float4* vn = (const float4*)&Wi[8 + ui][k0];
#pragma unroll
                for (int q = 0; q < 4; q++) {
                    float4 r4 = wr[q], z4 = wz[q], n4 = wn[q];
                    float4 s4 = vr[q], t4 = vz[q], u4 = vn[q];
                    float hw0 = hv[q*4+0], hw1 = hv[q*4+1], hw2 = hv[q*4+2], hw3 = hv[q*4+3];
                    float ew0 = ev[q*4+0], ew1 = ev[q*4+1], ew2 = ev[q*4+2], ew3 = ev[q*4+3];
                    hR = fmaf(hw0, r4.x, hR); hR = fmaf(hw1, r4.y, hR);
                    hR = fmaf(hw2, r4.z, hR); hR = fmaf(hw3, r4.w, hR);
                    hZ = fmaf(hw0, z4.x, hZ); hZ = fmaf(hw1, z4.y, hZ);
                    hZ = fmaf(hw2, z4.z, hZ); hZ = fmaf(hw3, z4.w, hZ);
                    hN = fmaf(hw0, n4.x, hN); hN = fmaf(hw1, n4.y, hN);
                    hN = fmaf(hw2, n4.z, hN); hN = fmaf(hw3, n4.w, hN);
                    iR = fmaf(ew0, s4.x, iR); iR = fmaf(ew1, s4.y, iR);
                    iR = fmaf(ew2, s4.z, iR); iR = fmaf(ew3, s4.w, iR);
                    iZ = fmaf(ew0, t4.x, iZ); iZ = fmaf(ew1, t4.y, iZ);
                    iZ = fmaf(ew2, t4.z, iZ); iZ = fmaf(ew3, t4.w, iZ);
                    iN = fmaf(ew0, u4.x, iN); iN = fmaf(ew1, u4.y, iN);
                    iN = fmaf(ew2, u4.z, iN); iN = fmaf(ew3, u4.w, iN);
                }
#pragma unroll
                for (int kk = 0; kk < 16; kk++) { hv[kk] = hv2[kk]; ev[kk] = ev2[kk]; }
            }

            float r = 1.f / (1.f + expf(-(iR + bhR + hR)));
            float z = 1.f / (1.f + expf(-(iZ + bhZ + hZ)));
            float n = tanhf(iN + r * (bhN + hN));
            float hp = __ldcg(hin + (size_t)u * 64 + b);
            float hn = (1.f - z) * n + z * hp;
            hout[(size_t)u * 64 + b] = hn;

            float hs = hn * SCL_MAIN;
            unsigned short s1 = f2h(hs);
            unsigned short s2 = f2h((hs - h2f(s1)) * SCL_RES);
            g_h1[(size_t)b * HID + u] = s1;
            g_h2[(size_t)b * HID + u] = s2;
        }
        grid_bar(++ep);

        // ---- phase C: logits GEMM + bias + argmax (3-stage pipeline) ----
        if (cta < LG_CTAS) {
            const int nblk = cta * LG_NT;
            const int g = lane >> 2, q4 = (lane & 3) * 4;
            float* ostep = out + (size_t)s * BSZ * VOC;

            float cm[4][4][4], cr[4][4][4];
#pragma unroll
            for (int i = 0; i < 4; i++)
#pragma unroll
                for (int j = 0; j < 4; j++)
#pragma unroll
                    for (int e = 0; e < 4; e++) { cm[i][j][e] = 0.f; cr[i][j][e] = 0.f; }

#define LG_ISSUE(kc) do {                                                      \
    char* buf = lsm + (size_t)((kc) % 3) * SBUF;                               \
    for (int i = tid; i < 2560; i += 256) {                                    \
        const unsigned short* src; char* dst;                                  \
        if (i < 2048) {                                                        \
            int p = i >> 10, rr = (i >> 2) & 255, q = i & 3;                   \
            const unsigned short* wp = p ? g_W2 : g_W1;                        \
            src = wp + (size_t)(nblk + rr) * HID + (kc) * KC + q * 8;          \
            dst = buf + (p * 256 + rr) * ROWB + q * 16;                        \
        } else {                                                               \
            int jj = i - 2048;                                                 \
            int p = jj >> 8, rr = (jj >> 2) & 63, q = jj & 3;                  \
            const unsigned short* hp = p ? g_h2 : g_h1;                        \
            src = hp + (size_t)rr * HID + (kc) * KC + q * 8;                   \
            dst = buf + A_OFF + (p * 64 + rr) * ROWB + q * 16;                 \
        }                                                                      \
        uint32_t d32 = smem_u32(dst);                                          \
        asm volatile("cp.async.cg.shared.global [%0], [%1], 16;"               \
                     :: "r"(d32), "l"(src));                                   \
    }                                                                          \
    asm volatile("cp.async.commit_group;");                                    \
} while (0)

            LG_ISSUE(0);
            LG_ISSUE(1);
#pragma unroll 1
            for (int kc = 0; kc < 16; kc++) {
                if (kc < 14) {
                    LG_ISSUE(kc + 2);
                    asm volatile("cp.async.wait_group 2;");
                } else if (kc == 14) {
                    asm volatile("cp.async.wait_group 1;");
                } else {
                    asm volatile("cp.async.wait_group 0;");
                }
                __syncthreads();
                const char* buf = lsm + (size_t)(kc % 3) * SBUF;
#pragma unroll
                for (int k16 = 0; k16 < 2; k16++) {
                    const int kb = k16 * 32 + q4;
                    uint32_t w1b0[4], w1b1[4], w2b0[4], w2b1[4];
#pragma unroll
                    for (int nt = 0; nt < 4; nt++) {
                        const char* bp0 = buf + (size_t)(      w * 32 + nt * 8 + g) * ROWB + kb;
                        const char* bp1 = buf + (size_t)(256 + w * 32 + nt * 8 + g) * ROWB + kb;
                        w1b0[nt] = *(const uint32_t*)bp0;
                        w1b1[nt] = *(const uint32_t*)(bp0 + 16);
                        w2b0[nt] = *(const uint32_t*)bp1;
                        w2b1[nt] = *(const uint32_t*)(bp1 + 16);
                    }
#pragma unroll
                    for (int mt = 0; mt < 4; mt++) {
                        const char* ap1 = buf + A_OFF + (size_t)(     mt * 16 + g) * ROWB + kb;
                        const char* ap2 = buf + A_OFF + (size_t)(64 + mt * 16 + g) * ROWB + kb;
                        uint32_t h1a0 = *(const uint32_t*)ap1;
                        uint32_t h1a1 = *(const uint32_t*)(ap1 + 8 * ROWB);
                        uint32_t h1a2 = *(const uint32_t*)(ap1 + 16);
                        uint32_t h1a3 = *(const uint32_t*)(ap1 + 8 * ROWB + 16);
                        uint32_t h2a0 = *(const uint32_t*)ap2;
                        uint32_t h2a1 = *(const uint32_t*)(ap2 + 8 * ROWB);
                        uint32_t h2a2 = *(const uint32_t*)(ap2 + 16);
                        uint32_t h2a3 = *(const uint32_t*)(ap2 + 8 * ROWB + 16);
#pragma unroll
                        for (int nt = 0; nt < 4; nt++) {
                            MMA16816(cm[mt][nt], h1a0, h1a1, h1a2, h1a3, w1b0[nt], w1b1[nt]);
                            MMA16816(cr[mt][nt], h1a0, h1a1, h1a2, h1a3, w2b0[nt], w2b1[nt]);
                            MMA16816(cr[mt][nt], h2a0, h2a1, h2a2, h2a3, w1b0[nt], w1b1[nt]);
                        }
                    }
                }
            }
#undef LG_ISSUE

#pragma unroll
            for (int mt = 0; mt < 4; mt++) {
                const int m0 = mt * 16 + g, m1 = m0 + 8;
                unsigned long long key0 = 0ull, key1 = 0ull;
#pragma unroll
                for (int nt = 0; nt < 4; nt++) {
                    const int col = nblk + w * 32 + nt * 8 + (lane & 3) * 2;
                    const float bb0 = bias[col], bb1 = bias[col + 1];
                    float v00 = cm[mt][nt][0] * INV_MAIN + cr[mt][nt][0] * INV_RES + bb0;
                    float v01 = cm[mt][nt][1] * INV_MAIN + cr[mt][nt][1] * INV_RES + bb1;
                    float v10 = cm[mt][nt][2] * INV_MAIN + cr[mt][nt][2] * INV_RES + bb0;
                    float v11 = cm[mt][nt][3] * INV_MAIN + cr[mt][nt][3] * INV_RES + bb1;
                    *(float2*)(ostep + (size_t)m0 * VOC + col) = make_float2(v00, v01);
                    *(float2*)(ostep + (size_t)m1 * VOC + col) = make_float2(v10, v11);
                    unsigned long long k00 = pack_key(v00, col);
                    unsigned long long k01 = pack_key(v01, col + 1);
                    unsigned long long k10 = pack_key(v10, col);
                    unsigned long long k11 = pack_key(v11, col + 1);
                    if (k00 > key0) key0 = k00;
                    if (k01 > key0) key0 = k01;
                    if (k10 > key1) key1 = k10;
                    if (k11 > key1) key1 = k11;
                }
#pragma unroll
                for (int d = 1; d < 4; d <<= 1) {
                    unsigned long long o0 = __shfl_xor_sync(0xFFFFFFFFu, key0, d);
                    unsigned long long o1 = __shfl_xor_sync(0xFFFFFFFFu, key1, d);
                    if (o0 > key0) key0 = o0;
                    if (o1 > key1) key1 = o1;
                }
                if ((lane & 3) == 0) {
                    atomicMax(&g_amax2[(s + 1) & 1][m0], key0);
                    atomicMax(&g_amax2[(s + 1) & 1][m1], key1);
                }
            }
        }
        grid_bar(++ep);
    }
}

// ---------------- host orchestration --------------------------------------
extern "C" void kernel_launch(void* const* d_in, const int* in_sizes, int n_in,
                              void* d_out, int out_size) {
    const int*   batch_X = (const int*)d_in[0];
    const int*   lengths = (const int*)d_in[1];
    const float* emb_enc = (const float*)d_in[3];
    const float* Wih_e   = (const float*)d_in[4];
    const float* Whh_e   = (const float*)d_in[5];
    const float* bih_e   = (const float*)d_in[6];
    const float* bhh_e   = (const float*)d_in[7];
    const float* emb_dec = (const float*)d_in[8];
    const float* Wih_d   = (const float*)d_in[9];
    const float* Whh_d   = (const float*)d_in[10];
    const float* bih_d   = (const float*)d_in[11];
    const float* bhh_d   = (const float*)d_in[12];
    const float* Wout    = (const float*)d_in[13];
    const float* bout    = (const float*)d_in[14];
    float* out = (float*)d_out;
    const int steps = out_size / (BSZ * VOC);   // 32

    (void)in_sizes; (void)n_in;

    cudaFuncSetAttribute(decoder_persist_k,
                         cudaFuncAttributeMaxDynamicSharedMemorySize, DEC_SMEM);
    cudaFuncSetAttribute(pregemm_mma_k,
                         cudaFuncAttributeMaxDynamicSharedMemorySize, PG_SMEM);

    k_init<<<128, 256>>>(emb_dec);
    k_wsplit2<<<(VOC * HID / 4 + 255) / 256, 256>>>(Wout);
    k_esplit2<<<(VOC * HID / 4 + 255) / 256, 256>>>(emb_enc);
    k_wisplit2<<<(G3H * HID / 4 + 255) / 256, 256>>>(Wih_e);

    // encoder input pre-GEMM on tensor cores (scaled fp16 split, 3 passes)
    pregemm_mma_k<<<dim3(G3H / 128, TLEN), 256, PG_SMEM>>>(batch_X, bih_e);

    // encoder recurrence: single persistent kernel, 128 steps internally
    enc_persist_k<<<ENC_CTAS, 512>>>(Whh_e, bhh_e, lengths);
    // final hidden ends in g_hA

    // decoder: single persistent kernel, all steps internally
    decoder_persist_k<<<DEC_CTAS, 256, DEC_SMEM>>>(
        Wih_d, bih_d, Whh_d, bhh_d, emb_dec, bout, out, steps);
}

// round 15
// speedup vs baseline: 1.1137x; 1.0086x over previous
#include <cuda_runtime.h>
#include <cuda_fp16.h>
#include <math.h>
#include <stdint.h>

#define HID 512
#define BSZ 64
#define TLEN 128
#define VOC 32000
#define G3H 1536
#define ENC_CTAS 128
#define DEC_CTAS 128
#define BOS 2

// scaling for fp16 split planes (powers of 2: exact)
#define SCL_MAIN 32.0f
#define SCL_RES  64.0f
#define INV_MAIN (1.0f / 1024.0f)
#define INV_RES  (1.0f / 65536.0f)

// logits GEMM tiling (fp16 2-way split, 3 explicit passes)
#define LG_NT 256
#define LG_CTAS (VOC / LG_NT)     // 125
#define KC 32
#define ROWB 80
#define B_ROWS (2 * LG_NT)        // 512
#define A_ROWS (2 * BSZ)          // 128
#define SBUF ((B_ROWS + A_ROWS) * ROWB)   // 51200
#define A_OFF (B_ROWS * ROWB)             // 40960

// persistent decoder smem: [0,24576) Wh, [24576,49152) Wi, then 3 logits bufs
#define DEC_WSM 49152
#define DEC_SMEM (DEC_WSM + 3 * SBUF)     // 202752

// pre-GEMM tiling
#define PG_ROWB 80
#define PG_BROWS (2 * 128)
#define PG_AROWS (2 * 64)
#define PG_SBUF ((PG_BROWS + PG_AROWS) * PG_ROWB)  // 30720
#define PG_AOFF (PG_BROWS * PG_ROWB)               // 20480
#define PG_SMEM (2 * PG_SBUF)                      // 61440

// ---------------- packed f32x2 helpers (sm_100-family PTX) -----------------
#define PACK2(out, lo, hi) \
    asm("mov.b64 %0, {%1, %2};" : "=l"(out) : "f"(lo), "f"(hi))
#define FFMA2(acc, a, b) \
    asm("fma.rn.f32x2 %0, %1, %2, %0;" : "+l"(acc) : "l"(a), "l"(b))
#define UNPACK2(lo, hi, in) \
    asm("mov.b64 {%0, %1}, %2;" : "=f"(lo), "=f"(hi) : "l"(in))

// ---------------- scratch ----------------
__device__ float g_gi[TLEN * G3H * BSZ];
__device__ float g_hA[HID * BSZ];
__device__ float g_hB[HID * BSZ];
__device__ float g_eT[HID * BSZ];
__device__ __align__(16) unsigned short g_W1[VOC * HID];
__device__ __align__(16) unsigned short g_W2[VOC * HID];
__device__ __align__(16) unsigned short g_E1[VOC * HID];
__device__ __align__(16) unsigned short g_E2[VOC * HID];
__device__ __align__(16) unsigned short g_Wi1[G3H * HID];
__device__ __align__(16) unsigned short g_Wi2[G3H * HID];
__device__ __align__(16) unsigned short g_h1[BSZ * HID];
__device__ __align__(16) unsigned short g_h2[BSZ * HID];
__device__ unsigned long long g_amax2[2][BSZ];
__device__ unsigned g_bar_cnt;
__device__ unsigned g_bar_rel;
__device__ unsigned g_dcnt;
__device__ unsigned g_drel;

__device__ __forceinline__ unsigned ordered_f32(float f) {
    unsigned u = __float_as_uint(f);
    return (u & 0x80000000u) ? ~u : (u | 0x80000000u);
}
__device__ __forceinline__ unsigned short f2h(float x) {
    __half t = __float2half_rn(x);
    return *(unsigned short*)&t;
}
__device__ __forceinline__ float h2f(unsigned short u) {
    __half t = *(__half*)&u;
    return __half2float(t);
}
__device__ __forceinline__ uint32_t smem_u32(const void* p) {
    uint32_t a;
    asm("{ .reg .u64 t; cvta.to.shared.u64 t, %1; cvt.u32.u64 %0, t; }"
        : "=r"(a) : "l"(p));
    return a;
}
__device__ __forceinline__ unsigned long long pack_key(float v, int idx) {
    return ((unsigned long long)ordered_f32(v) << 32) |
           (unsigned long long)(0xFFFFFFFFu - (unsigned)idx);
}

#define MMA16816(C, A0, A1, A2, A3, B0, B1) \
    asm volatile("mma.sync.aligned.m16n8k16.row.col.f32.f16.f16.f32 " \
        "{%0,%1,%2,%3}, {%4,%5,%6,%7}, {%8,%9}, {%0,%1,%2,%3};" \
        : "+f"((C)[0]), "+f"((C)[1]), "+f"((C)[2]), "+f"((C)[3]) \
        : "r"(A0), "r"(A1), "r"(A2), "r"(A3), "r"(B0), "r"(B1))

// grid barrier for the persistent decoder (epoch-monotonic)
__device__ __forceinline__ void grid_bar(unsigned ep) {
    __threadfence();
    __syncthreads();
    if (threadIdx.x == 0) {
        unsigned v = atomicAdd(&g_dcnt, 1u);
        if (v == DEC_CTAS - 1) {
            atomicExch(&g_dcnt, 0u);
            __threadfence();
            atomicAdd(&g_drel, 1u);
        }
        while (atomicAdd(&g_drel, 0u) < ep) {}
    }
    __syncthreads();
}

// ---------------- init ----------------------------------------------------
__global__ void k_init(const float* __restrict__ emb_dec) {
    int idx = blockIdx.x * blockDim.x + threadIdx.x;
    if (idx < HID * BSZ) {
        g_hA[idx] = 0.f;
        g_eT[idx] = emb_dec[BOS * HID + (idx >> 6)];   // BOS embedding, transposed
    }
    if (idx < BSZ) { g_amax2[0][idx] = 0ull; g_amax2[1][idx] = 0ull; }
    if (idx == 0) { g_bar_cnt = 0u; g_bar_rel = 0u; g_dcnt = 0u; g_drel = 0u; }
}

// ---------------- scaled 2-way fp16 splits (row-major, device-direct) ------
__global__ void k_wsplit2(const float* __restrict__ W) {
    size_t i = ((size_t)blockIdx.x * 256 + threadIdx.x) * 4;
    if (i >= (size_t)VOC * HID) return;
    float4 v = *(const float4*)(W + i);
    float a[4] = {v.x, v.y, v.z, v.w};
#pragma unroll
    for (int j = 0; j < 4; j++) {
        float xs = a[j] * SCL_MAIN;
        unsigned short s1 = f2h(xs);
        unsigned short s2 = f2h((xs - h2f(s1)) * SCL_RES);
        g_W1[i + j] = s1; g_W2[i + j] = s2;
    }
}
__global__ void k_esplit2(const float* __restrict__ E) {
    size_t i = ((size_t)blockIdx.x * 256 + threadIdx.x) * 4;
    if (i >= (size_t)VOC * HID) return;
    float4 v = *(const float4*)(E + i);
    float a[4] = {v.x, v.y, v.z, v.w};
#pragma unroll
    for (int j = 0; j < 4; j++) {
        float xs = a[j] * SCL_MAIN;
        unsigned short s1 = f2h(xs);
        unsigned short s2 = f2h((xs - h2f(s1)) * SCL_RES);
        g_E1[i + j] = s1; g_E2[i + j] = s2;
    }
}
__global__ void k_wisplit2(const float* __restrict__ Wi) {
    size_t i = ((size_t)blockIdx.x * 256 + threadIdx.x) * 4;
    if (i >= (size_t)G3H * HID) return;
    float4 v = *(const float4*)(Wi + i);
    float a[4] = {v.x, v.y, v.z, v.w};
#pragma unroll
    for (int j = 0; j < 4; j++) {
        float xs = a[j] * SCL_MAIN;
        unsigned short s1 = f2h(xs);
        unsigned short s2 = f2h((xs - h2f(s1)) * SCL_RES);
        g_Wi1[i + j] = s1; g_Wi2[i + j] = s2;
    }
}

// ---------------- pre-GEMM via mma.sync (R11-proven) -----------------------
__global__ void __launch_bounds__(256, 1) pregemm_mma_k(
    const int* __restrict__ tokens, const float* __restrict__ bias)
{
    extern __shared__ __align__(128) char smem[];
    __shared__ int s_tok[64];
    const int tid = threadIdx.x, lane = tid & 31, w = tid >> 5;
    const int nblk = blockIdx.x * 128;
    const int t = blockIdx.y;
    const int g = lane >> 2, q4 = (lane & 3) * 4;

    if (tid < 64) s_tok[tid] = tokens[t * 64 + tid];
    __syncthreads();

    float cm[4][2][4], cr[4][2][4];
#pragma unroll
    for (int i = 0; i < 4; i++)
#pragma unroll
        for (int j = 0; j < 2; j++)
#pragma unroll
            for (int e = 0; e < 4; e++) { cm[i][j][e] = 0.f; cr[i][j][e] = 0.f; }

#define PG_ISSUE(kc) do {                                                      \
    char* buf = smem + (size_t)((kc) & 1) * PG_SBUF;                           \
    for (int i = tid; i < 1536; i += 256) {                                    \
        const unsigned short* src; char* dst;                                  \
        if (i < 1024) {                                                        \
            int p = i >> 9, rr = (i >> 2) & 127, q = i & 3;                    \
            const unsigned short* wp = p ? g_Wi2 : g_Wi1;                      \
            src = wp + (size_t)(nblk + rr) * HID + (kc) * KC + q * 8;          \
            dst = buf + (p * 128 + rr) * PG_ROWB + q * 16;                     \
        } else {                                                               \
            int jj = i - 1024;                                                 \
            int p = jj >> 8, rr = (jj >> 2) & 63, q = jj & 3;                  \
            const unsigned short* ep = p ? g_E2 : g_E1;                        \
            src = ep + (size_t)s_tok[rr] * HID + (kc) * KC + q * 8;            \
            dst = buf + PG_AOFF + (p * 64 + rr) * PG_ROWB + q * 16;            \
        }                                                                      \
        uint32_t d32 = smem_u32(dst);                                          \
        asm volatile("cp.async.cg.shared.global [%0], [%1], 16;"               \
                     :: "r"(d32), "l"(src));                                   \
    }                                                                          \
    asm volatile("cp.async.commit_group;");                                    \
} while (0)

    PG_ISSUE(0);

#pragma unroll 1
    for (int kc = 0; kc < 16; kc++) {
        if (kc < 15) {
            PG_ISSUE(kc + 1);
            asm volatile("cp.async.wait_group 1;");
        } else {
            asm volatile("cp.async.wait_group 0;");
        }
        __syncthreads();
        const char* buf = smem + (size_t)(kc & 1) * PG_SBUF;
#pragma unroll
        for (int k16 = 0; k16 < 2; k16++) {
            const int kb = k16 * 32 + q4;
            uint32_t w1b0[2], w1b1[2], w2b0[2], w2b1[2];
#pragma unroll
            for (int nt = 0; nt < 2; nt++) {
                const char* bp0 = buf + (size_t)(      w * 16 + nt * 8 + g) * PG_ROWB + kb;
                const char* bp1 = buf + (size_t)(128 + w * 16 + nt * 8 + g) * PG_ROWB + kb;
                w1b0[nt] = *(const uint32_t*)bp0;
                w1b1[nt] = *(const uint32_t*)(bp0 + 16);
                w2b0[nt] = *(const uint32_t*)bp1;
                w2b1[nt] = *(const uint32_t*)(bp1 + 16);
            }
#pragma unroll
            for (int mt = 0; mt < 4; mt++) {
                const char* ap1 = buf + PG_AOFF + (size_t)(     mt * 16 + g) * PG_ROWB + kb;
                const char* ap2 = buf + PG_AOFF + (size_t)(64 + mt * 16 + g) * PG_ROWB + kb;
                uint32_t e1a0 = *(const uint32_t*)ap1;
                uint32_t e1a1 = *(const uint32_t*)(ap1 + 8 * PG_ROWB);
                uint32_t e1a2 = *(const uint32_t*)(ap1 + 16);
                uint32_t e1a3 = *(const uint32_t*)(ap1 + 8 * PG_ROWB + 16);
                uint32_t e2a0 = *(const uint32_t*)ap2;
                uint32_t e2a1 = *(const uint32_t*)(ap2 + 8 * PG_ROWB);
                uint32_t e2a2 = *(const uint32_t*)(ap2 + 16);
                uint32_t e2a3 = *(const uint32_t*)(ap2 + 8 * PG_ROWB + 16);
#pragma unroll
                for (int nt = 0; nt < 2; nt++) {
                    MMA16816(cm[mt][nt], e1a0, e1a1, e1a2, e1a3, w1b0[nt], w1b1[nt]);
                    MMA16816(cr[mt][nt], e1a0, e1a1, e1a2, e1a3, w2b0[nt], w2b1[nt]);
                    MMA16816(cr[mt][nt], e2a0, e2a1, e2a2, e2a3, w1b0[nt], w1b1[nt]);
                }
            }
        }
        __syncthreads();
    }
#undef PG_ISSUE

#pragma unroll
    for (int mt = 0; mt < 4; mt++) {
        const int m0 = mt * 16 + g, m1 = m0 + 8;
#pragma unroll
        for (int nt = 0; nt < 2; nt++) {
            const int n = nblk + w * 16 + nt * 8 + (lane & 3) * 2;
            const float bb0 = bias[n], bb1 = bias[n + 1];
            float* base = g_gi + ((size_t)t * G3H + n) * 64;
            base[m0]      = cm[mt][nt][0] * INV_MAIN + cr[mt][nt][0] * INV_RES + bb0;
            base[64 + m0] = cm[mt][nt][1] * INV_MAIN + cr[mt][nt][1] * INV_RES + bb1;
            base[m1]      = cm[mt][nt][2] * INV_MAIN + cr[mt][nt][2] * INV_RES + bb0;
            base[64 + m1] = cm[mt][nt][3] * INV_MAIN + cr[mt][nt][3] * INV_RES + bb1;
        }
    }
}

// ---------------- persistent encoder recurrence (512-thr, f32x2 FMA) -------
__global__ void __launch_bounds__(512, 1) enc_persist_k(
    const float* __restrict__ Whh, const float* __restrict__ bhh,
    const int* __restrict__ lengths)
{
    __shared__ float Wh[12][HID];
    __shared__ float part[3][4][64];
    const int tid = threadIdx.x;
    const int u0 = blockIdx.x * 4;

    for (int idx = tid; idx < 12 * HID; idx += 512) {
        int r = idx >> 9, k = idx & 511;
        int g = r >> 2, ui = r & 3;
        Wh[r][k] = Whh[(size_t)(g * HID + u0 + ui) * HID + k];
    }
    const int b    = tid & 63;
    const int half = (tid >> 6) & 1;
    const int ui   = tid >> 7;
    const int u    = u0 + ui;
    const int kb0  = half * 256;
    const float bR = bhh[u], bZ = bhh[HID + u], bN = bhh[2 * HID + u];
    const int len = lengths[b];
    __syncthreads();

#pragma unroll 1
    for (int t = 0; t < TLEN; t++) {
        const float* hin = (t & 1) ? g_hB : g_hA;
        float* hout      = (t & 1) ? g_hA : g_hB;
        const float* gi  = g_gi + (size_t)t * (G3H * 64);

        unsigned long long aR2 = 0ull, aZ2 = 0ull, aN2 = 0ull;

        float hv[16];
#pragma unroll
        for (int kk = 0; kk < 16; kk++) hv[kk] = __ldcg(hin + (kb0 + kk) * 64 + b);

#pragma unroll 2
        for (int k0 = 0; k0 < 256; k0 += 16) {
            float nv[16];
            const int kn = (k0 + 16 < 256) ? (k0 + 16) : 0;
#pragma unroll
            for (int kk = 0; kk < 16; kk++)
                nv[kk] = __ldcg(hin + (kb0 + kn + kk) * 64 + b);
            const unsigned long long* wr2 = (const unsigned long long*)&Wh[ui][kb0 + k0];
            const unsigned long long* wz2 = (const unsigned long long*)&Wh[4 + ui][kb0 + k0];
            const unsigned long long* wn2 = (const unsigned long long*)&Wh[8 + ui][kb0 + k0];
#pragma unroll
            for (int q = 0; q < 8; q++) {
                unsigned long long hp2;
                PACK2(hp2, hv[q * 2], hv[q * 2 + 1]);
                FFMA2(aR2, hp2, wr2[q]);
                FFMA2(aZ2, hp2, wz2[q]);
                FFMA2(aN2, hp2, wn2[q]);
            }
#pragma unroll
            for (int kk = 0; kk < 16; kk++) hv[kk] = nv[kk];
        }

        float rE, rO, zE, zO, nE, nO;
        UNPACK2(rE, rO, aR2); UNPACK2(zE, zO, aZ2); UNPACK2(nE, nO, aN2);
        float hR = rE + rO, hZ = zE + zO, hN = nE + nO;

        if (half) {
            part[0][ui][b] = hR; part[1][ui][b] = hZ; part[2][ui][b] = hN;
        }
        __syncthreads();
        if (!half) {
            hR += part[0][ui][b]; hZ += part[1][ui][b]; hN += part[2][ui][b];
            float giR = gi[(size_t)u * 64 + b];
            float giZ = gi[(size_t)(HID + u) * 64 + b];
            float giN = gi[(size_t)(2 * HID + u) * 64 + b];
            float r = 1.f / (1.f + expf(-(giR + bR + hR)));
            float z = 1.f / (1.f + expf(-(giZ + bZ + hZ)));
            float n = tanhf(giN + r * (bN + hN));
            float hp = __ldcg(hin + (size_t)u * 64 + b);
            float hn = (1.f - z) * n + z * hp;
            if (t >= len) hn = hp;
            hout[(size_t)u * 64 + b] = hn;
        }

        if (t < TLEN - 1) {
            __threadfence();
            __syncthreads();
            if (tid == 0) {
                unsigned v = atomicAdd(&g_bar_cnt, 1u);
                if (v == ENC_CTAS - 1) {
                    atomicExch(&g_bar_cnt, 0u);
                    atomicAdd(&g_bar_rel, 1u);
                }
                while (atomicAdd(&g_bar_rel, 0u) < (unsigned)(t + 1)) {}
            }
            __syncthreads();
        }
    }
}

// ---------------- persistent decoder (R14 structure; f32x2 phase B) --------
__global__ void __launch_bounds__(256, 1) decoder_persist_k(
    const float* __restrict__ Wih, const float* __restrict__ bih,
    const float* __restrict__ Whh, const float* __restrict__ bhh,
    const float* __restrict__ emb_dec, const float* __restrict__ bias,
    float* __restrict__ out, int steps)
{
    extern __shared__ __align__(128) char smem[];
    float (*Wh)[HID] = (float(*)[HID])(smem);
    float (*Wi)[HID] = (float(*)[HID])(smem + 24576);
    char* lsm = smem + DEC_WSM;
    __shared__ int s_tok;

    const int tid = threadIdx.x, lane = tid & 31, w = tid >> 5;
    const int cta = blockIdx.x;
    const int u0 = cta * 4;
    unsigned ep = 0;

    for (int idx = tid; idx < 12 * HID; idx += 256) {
        int r = idx >> 9, k = idx & 511;
        int g = r >> 2, ui = r & 3;
        size_t wrow = (size_t)(g * HID + u0 + ui) * HID + k;
        Wh[r][k] = Whh[wrow];
        Wi[r][k] = Wih[wrow];
    }
    const int b  = tid & 63;
    const int ui = tid >> 6;
    const int u  = u0 + ui;
    const float bhR = bhh[u], bhZ = bhh[HID + u], bhN = bhh[2 * HID + u];
    const float biR = bih[u], biZ = bih[HID + u], biN = bih[2 * HID + u];
    __syncthreads();

#pragma unroll 1
    for (int s = 0; s < steps; s++) {
        // ---- phase A: argmax finalize + embedding gather ----
        if (s > 0) {
            if (cta < BSZ) {
                if (tid == 0) {
                    unsigned long long key = atomicAdd(&g_amax2[s & 1][cta], 0ull);
                    s_tok = (int)(0xFFFFFFFFu - (unsigned)(key & 0xFFFFFFFFull));
                    atomicExch(&g_amax2[s & 1][cta], 0ull);
                }
                __syncthreads();
                const float* src = emb_dec + (size_t)s_tok * HID;
#pragma unroll
                for (int k = tid; k < HID; k += 256)
                    g_eT[(size_t)k * 64 + cta] = src[k];
            }
            grid_bar(++ep);
        }

        // ---- phase B: fused GRU step (f32x2 packed FMA) ----
        {
            const float* hin = (s & 1) ? g_hB : g_hA;
            float* hout      = (s & 1) ? g_hA : g_hB;
            unsigned long long hR2 = 0ull, hZ2 = 0ull, hN2 = 0ull;
            unsigned long long iR2 = 0ull, iZ2 = 0ull, iN2 = 0ull;

            float hv[16], ev[16];
#pragma unroll
            for (int kk = 0; kk < 16; kk++) {
                hv[kk] = __ldcg(hin  + kk * 64 + b);
                ev[kk] = __ldcg(g_eT + kk * 64 + b);
            }

#pragma unroll 2
            for (int k0 = 0; k0 < HID; k0 += 16) {
                float hv2[16], ev2[16];
                const int kn = (k0 + 16 < HID) ? (k0 + 16) : 0;
#pragma unroll
                for (int kk = 0; kk < 16; kk++) {
                    hv2[kk] = __ldcg(hin  + (kn + kk) * 64 + b);
                    ev2[kk] = __ldcg(g_eT + (kn + kk) * 64 + b);
                }
                const unsigned long long* wr2 = (const unsigned long long*)&Wh[ui][k0];
                const unsigned long long* wz2 = (const unsigned long long*)&Wh[4 + ui][k0];
                const unsigned long long* wn2 = (const unsigned long long*)&Wh[8 + ui][k0];
                const unsigned long long* vr2 = (const unsigned long long*)&Wi[ui][k0];
                const unsigned long long* vz2 = (const unsigned long long*)&Wi[4 + ui][k0];
                const unsigned long long* vn2 = (const unsigned long long*)&Wi[8 + ui][k0];
#pragma unroll
                for (int q = 0; q < 8; q++) {
                    unsigned long long hp2, ep2;
                    PACK2(hp2, hv[q * 2], hv[q * 2 + 1]);
                    PACK2(ep2, ev[q * 2], ev[q * 2 + 1]);
                    FFMA2(hR2, hp2, wr2[q]);
                    FFMA2(hZ2, hp2, wz2[q]);
                    FFMA2(hN2, hp2, wn2[q]);
                    FFMA2(iR2, ep2, vr2[q]);
                    FFMA2(iZ2, ep2, vz2[q]);
                    FFMA2(iN2, ep2, vn2[q]);
                }
#pragma unroll
                for (int kk = 0; kk < 16; kk++) { hv[kk] = hv2[kk]; ev[kk] = ev2[kk]; }
            }

            float e0, e1;
            UNPACK2(e0, e1, hR2); float hR = e0 + e1;
            UNPACK2(e0, e1, hZ2); float hZ = e0 + e1;
            UNPACK2(e0, e1, hN2); float hN = e0 + e1;
            UNPACK2(e0, e1, iR2); float iR = e0 + e1 + biR;
            UNPACK2(e0, e1, iZ2); float iZ = e0 + e1 + biZ;
            UNPACK2(e0, e1, iN2); float iN = e0 + e1 + biN;

            float r = 1.f / (1.f + expf(-(iR + bhR + hR)));
            float z = 1.f / (1.f + expf(-(iZ + bhZ + hZ)));
            float n = tanhf(iN + r * (bhN + hN));
            float hp = __ldcg(hin + (size_t)u * 64 + b);
            float hn = (1.f - z) * n + z * hp;
            hout[(size_t)u * 64 + b] = hn;

            float hs = hn * SCL_MAIN;
            unsigned short s1 = f2h(hs);
            unsigned short s2 = f2h((hs - h2f(s1)) * SCL_RES);
            g_h1[(size_t)b * HID + u] = s1;
            g_h2[(size_t)b * HID + u] = s2;
        }
        grid_bar(++ep);

        // ---- phase C: logits GEMM + bias + argmax (3-stage pipeline) ----
        if (cta < LG_CTAS) {
            const int nblk = cta * LG_NT;
            const int g = lane >> 2, q4 = (lane & 3) * 4;
            float* ostep = out + (size_t)s * BSZ * VOC;

            float cm[4][4][4], cr[4][4][4];
#pragma unroll
            for (int i = 0; i < 4; i++)
#pragma unroll
                for (int j = 0; j < 4; j++)
#pragma unroll
                    for (int e = 0; e < 4; e++) { cm[i][j][e] = 0.f; cr[i][j][e] = 0.f; }

#define LG_ISSUE(kc) do {                                                      \
    char* buf = lsm + (size_t)((kc) % 3) * SBUF;                               \
    for (int i = tid; i < 2560; i += 256) {                                    \
        const unsigned short* src; char* dst;                                  \
        if (i < 2048) {                                                        \
            int p = i >> 10, rr = (i >> 2) & 255, q = i & 3;                   \
            const unsigned short* wp = p ? g_W2 : g_W1;                        \
            src = wp + (size_t)(nblk + rr) * HID + (kc) * KC + q * 8;          \
            dst = buf + (p * 256 + rr) * ROWB + q * 16;                        \
        } else {                                                               \
            int jj = i - 2048;                                                 \
            int p = jj >> 8, rr = (jj >> 2) & 63, q = jj & 3;                  \
            const unsigned short* hp = p ? g_h2 : g_h1;                        \
            src = hp + (size_t)rr * HID + (kc) * KC + q * 8;                   \
            dst = buf + A_OFF + (p * 64 + rr) * ROWB + q * 16;                 \
        }                                                                      \
        uint32_t d32 = smem_u32(dst);                                          \
        asm volatile("cp.async.cg.shared.global [%0], [%1], 16;"               \
                     :: "r"(d32), "l"(src));                                   \
    }                                                                          \
    asm volatile("cp.async.commit_group;");                                    \
} while (0)

            LG_ISSUE(0);
            LG_ISSUE(1);
#pragma unroll 1
            for (int kc = 0; kc < 16; kc++) {
                if (kc < 14) {
                    LG_ISSUE(kc + 2);
                    asm volatile("cp.async.wait_group 2;");
                } else if (kc == 14) {
                    asm volatile("cp.async.wait_group 1;");
                } else {
                    asm volatile("cp.async.wait_group 0;");
                }
                __syncthreads();
                const char* buf = lsm + (size_t)(kc % 3) * SBUF;
#pragma unroll
                for (int k16 = 0; k16 < 2; k16++) {
                    const int kb = k16 * 32 + q4;
                    uint32_t w1b0[4], w1b1[4], w2b0[4], w2b1[4];
#pragma unroll
                    for (int nt = 0; nt < 4; nt++) {
                        const char* bp0 = buf + (size_t)(      w * 32 + nt * 8 + g) * ROWB + kb;
                        const char* bp1 = buf + (size_t)(256 + w * 32 + nt * 8 + g) * ROWB + kb;
                        w1b0[nt] = *(const uint32_t*)bp0;
                        w1b1[nt] = *(const uint32_t*)(bp0 + 16);
                        w2b0[nt] = *(const uint32_t*)bp1;
                        w2b1[nt] = *(const uint32_t*)(bp1 + 16);
                    }
#pragma unroll
                    for (int mt = 0; mt < 4; mt++) {
                        const char* ap1 = buf + A_OFF + (size_t)(     mt * 16 + g) * ROWB + kb;
                        const char* ap2 = buf + A_OFF + (size_t)(64 + mt * 16 + g) * ROWB + kb;
                        uint32_t h1a0 = *(const uint32_t*)ap1;
                        uint32_t h1a1 = *(const uint32_t*)(ap1 + 8 * ROWB);
                        uint32_t h1a2 = *(const uint32_t*)(ap1 + 16);
                        uint32_t h1a3 = *(const uint32_t*)(ap1 + 8 * ROWB + 16);
                        uint32_t h2a0 = *(const uint32_t*)ap2;
                        uint32_t h2a1 = *(const uint32_t*)(ap2 + 8 * ROWB);
                        uint32_t h2a2 = *(const uint32_t*)(ap2 + 16);
                        uint32_t h2a3 = *(const uint32_t*)(ap2 + 8 * ROWB + 16);
#pragma unroll
                        for (int nt = 0; nt < 4; nt++) {
                            MMA16816(cm[mt][nt], h1a0, h1a1, h1a2, h1a3, w1b0[nt], w1b1[nt]);
                            MMA16816(cr[mt][nt], h1a0, h1a1, h1a2, h1a3, w2b0[nt], w2b1[nt]);
                            MMA16816(cr[mt][nt], h2a0, h2a1, h2a2, h2a3, w1b0[nt], w1b1[nt]);
                        }
                    }
                }
            }
#undef LG_ISSUE

#pragma unroll
            for (int mt = 0; mt < 4; mt++) {
                const int m0 = mt * 16 + g, m1 = m0 + 8;
                unsigned long long key0 = 0ull, key1 = 0ull;
#pragma unroll
                for (int nt = 0; nt < 4; nt++) {
                    const int col = nblk + w * 32 + nt * 8 + (lane & 3) * 2;
                    const float bb0 = bias[col], bb1 = bias[col + 1];
                    float v00 = cm[mt][nt][0] * INV_MAIN + cr[mt][nt][0] * INV_RES + bb0;
                    float v01 = cm[mt][nt][1] * INV_MAIN + cr[mt][nt][1] * INV_RES + bb1;
                    float v10 = cm[mt][nt][2] * INV_MAIN + cr[mt][nt][2] * INV_RES + bb0;
                    float v11 = cm[mt][nt][3] * INV_MAIN + cr[mt][nt][3] * INV_RES + bb1;
                    *(float2*)(ostep + (size_t)m0 * VOC + col) = make_float2(v00, v01);
                    *(float2*)(ostep + (size_t)m1 * VOC + col) = make_float2(v10, v11);
                    unsigned long long k00 = pack_key(v00, col);
                    unsigned long long k01 = pack_key(v01, col + 1);
                    unsigned long long k10 = pack_key(v10, col);
                    unsigned long long k11 = pack_key(v11, col + 1);
                    if (k00 > key0) key0 = k00;
                    if (k01 > key0) key0 = k01;
                    if (k10 > key1) key1 = k10;
                    if (k11 > key1) key1 = k11;
                }
#pragma unroll
                for (int d = 1; d < 4; d <<= 1) {
                    unsigned long long o0 = __shfl_xor_sync(0xFFFFFFFFu, key0, d);
                    unsigned long long o1 = __shfl_xor_sync(0xFFFFFFFFu, key1, d);
                    if (o0 > key0) key0 = o0;
                    if (o1 > key1) key1 = o1;
                }
                if ((lane & 3) == 0) {
                    atomicMax(&g_amax2[(s + 1) & 1][m0], key0);
                    atomicMax(&g_amax2[(s + 1) & 1][m1], key1);
                }
            }
        }
        grid_bar(++ep);
    }
}

// ---------------- host orchestration --------------------------------------
extern "C" void kernel_launch(void* const* d_in, const int* in_sizes, int n_in,
                              void* d_out, int out_size) {
    const int*   batch_X = (const int*)d_in[0];
    const int*   lengths = (const int*)d_in[1];
    const float* emb_enc = (const float*)d_in[3];
    const float* Wih_e   = (const float*)d_in[4];
    const float* Whh_e   = (const float*)d_in[5];
    const float* bih_e   = (const float*)d_in[6];
    const float* bhh_e   = (const float*)d_in[7];
    const float* emb_dec = (const float*)d_in[8];
    const float* Wih_d   = (const float*)d_in[9];
    const float* Whh_d   = (const float*)d_in[10];
    const float* bih_d   = (const float*)d_in[11];
    const float* bhh_d   = (const float*)d_in[12];
    const float* Wout    = (const float*)d_in[13];
    const float* bout    = (const float*)d_in[14];
    float* out = (float*)d_out;
    const int steps = out_size / (BSZ * VOC);   // 32

    (void)in_sizes; (void)n_in;

    cudaFuncSetAttribute(decoder_persist_k,
                         cudaFuncAttributeMaxDynamicSharedMemorySize, DEC_SMEM);
    cudaFuncSetAttribute(pregemm_mma_k,
                         cudaFuncAttributeMaxDynamicSharedMemorySize, PG_SMEM);

    k_init<<<128, 256>>>(emb_dec);
    k_wsplit2<<<(VOC * HID / 4 + 255) / 256, 256>>>(Wout);
    k_esplit2<<<(VOC * HID / 4 + 255) / 256, 256>>>(emb_enc);
    k_wisplit2<<<(G3H * HID / 4 + 255) / 256, 256>>>(Wih_e);

    // encoder input pre-GEMM on tensor cores (scaled fp16 split, 3 passes)
    pregemm_mma_k<<<dim3(G3H / 128, TLEN), 256, PG_SMEM>>>(batch_X, bih_e);

    // encoder recurrence: single persistent kernel, 128 steps internally
    enc_persist_k<<<ENC_CTAS, 512>>>(Whh_e, bhh_e, lengths);
    // final hidden ends in g_hA

    // decoder: single persistent kernel, all steps internally
    decoder_persist_k<<<DEC_CTAS, 256, DEC_SMEM>>>(
        Wih_d, bih_d, Whh_d, bhh_d, emb_dec, bout, out, steps);
}